// round 8
// baseline (speedup 1.0000x reference)
#include <cuda_runtime.h>
#include <cuda_bf16.h>
#include <math.h>
#include <stdint.h>

#define BATCH 8
#define C_IN 256
#define C_I  128
#define NN   4096
#define MM   1024

// ---------------------------------------------------------------------------
// Scratch: bf16 hi/lo operand planes + fp32 outputs
// ---------------------------------------------------------------------------
__device__ __align__(16) __nv_bfloat16 d_xTh[BATCH][NN][C_IN];
__device__ __align__(16) __nv_bfloat16 d_xTl[BATCH][NN][C_IN];
__device__ __align__(16) __nv_bfloat16 d_thh[BATCH][NN][C_I];
__device__ __align__(16) __nv_bfloat16 d_thl[BATCH][NN][C_I];
__device__ __align__(16) __nv_bfloat16 d_phh[BATCH][MM][C_I];
__device__ __align__(16) __nv_bfloat16 d_phl[BATCH][MM][C_I];
__device__ __align__(16) __nv_bfloat16 d_gh [BATCH][C_I][MM];
__device__ __align__(16) __nv_bfloat16 d_gl [BATCH][C_I][MM];
__device__ __align__(16) __nv_bfloat16 d_yh [BATCH][NN][C_I];
__device__ __align__(16) __nv_bfloat16 d_yl [BATCH][NN][C_I];
__device__ __align__(16) __nv_bfloat16 d_wthh[C_I][C_IN], d_wthl[C_I][C_IN];
__device__ __align__(16) __nv_bfloat16 d_wphh[C_I][C_IN], d_wphl[C_I][C_IN];
__device__ __align__(16) __nv_bfloat16 d_wgh [C_I][C_IN], d_wgl [C_I][C_IN];
__device__ __align__(16) __nv_bfloat16 d_wwh [C_IN][C_I], d_wwl [C_IN][C_I];

__device__ float d_wy [BATCH][C_IN][NN];
__device__ float d_bns [BATCH][C_IN][128];
__device__ float d_bnss[BATCH][C_IN][128];
__device__ float d_scale[C_IN];
__device__ float d_shift[C_IN];

// ---------------------------------------------------------------------------
// helpers
// ---------------------------------------------------------------------------
__device__ __forceinline__ uint32_t smem_u32(const void* p) {
    uint32_t a;
    asm("{ .reg .u64 t; cvta.to.shared.u64 t, %1; cvt.u32.u64 %0, t; }" : "=r"(a) : "l"(p));
    return a;
}

#define LDSM_X4(r0, r1, r2, r3, addr) \
    asm volatile("ldmatrix.sync.aligned.m8n8.x4.shared.b16 {%0,%1,%2,%3}, [%4];" \
        : "=r"(r0), "=r"(r1), "=r"(r2), "=r"(r3) : "r"(addr))

#define MMA_BF16(c, a, b) \
    asm volatile("mma.sync.aligned.m16n8k16.row.col.f32.bf16.bf16.f32 " \
        "{%0,%1,%2,%3}, {%4,%5,%6,%7}, {%8,%9}, {%0,%1,%2,%3};" \
        : "+f"((c)[0]), "+f"((c)[1]), "+f"((c)[2]), "+f"((c)[3]) \
        : "r"((a)[0]), "r"((a)[1]), "r"((a)[2]), "r"((a)[3]), "r"((b)[0]), "r"((b)[1]))

#define CP_COMMIT()  asm volatile("cp.async.commit_group;" ::: "memory")
#define CP_WAIT(n)   asm volatile("cp.async.wait_group %0;" :: "n"(n) : "memory")

__device__ __forceinline__ uint32_t pack2(float a, float b, uint32_t& lo)
{
    __nv_bfloat16 ha = __float2bfloat16(a), hb = __float2bfloat16(b);
    __nv_bfloat16 la = __float2bfloat16(a - __bfloat162float(ha));
    __nv_bfloat16 lb = __float2bfloat16(b - __bfloat162float(hb));
    lo = ((uint32_t)__bfloat16_as_ushort(lb) << 16) | __bfloat16_as_ushort(la);
    return ((uint32_t)__bfloat16_as_ushort(hb) << 16) | __bfloat16_as_ushort(ha);
}

__device__ __forceinline__ void split1(float v, __nv_bfloat16& h, __nv_bfloat16& l)
{
    h = __float2bfloat16(v);
    l = __float2bfloat16(v - __bfloat162float(h));
}

#define T_STRIDE 80
#define T_BYTES  (128 * T_STRIDE)            // 10240  (128-row tile)
#define T64_BYTES (64 * T_STRIDE)            // 5120   (64-row tile)
#define DSM_GEMM (3 * 4 * T_BYTES + 128)
#define STG_LD   132

// async copy one 128x32 bf16 tile (2 x 16B per thread)
__device__ __forceinline__ void casync_tile(uint32_t dst, const __nv_bfloat16* __restrict__ src,
                                            int ld, int tid)
{
    #pragma unroll
    for (int i = 0; i < 2; i++) {
        int c = tid * 2 + i;
        int r = c >> 2, q = c & 3;
        const __nv_bfloat16* gp = src + (size_t)r * ld + q * 8;
        uint32_t sp = dst + (uint32_t)(r * T_STRIDE + q * 16);
        asm volatile("cp.async.cg.shared.global [%0], [%1], 16;" :: "r"(sp), "l"(gp) : "memory");
    }
}

// async copy one 64x32 bf16 tile (1 x 16B per thread)
__device__ __forceinline__ void casync_tile64(uint32_t dst, const __nv_bfloat16* __restrict__ src,
                                              int ld, int tid)
{
    int r = tid >> 2, q = tid & 3;
    const __nv_bfloat16* gp = src + (size_t)r * ld + q * 8;
    uint32_t sp = dst + (uint32_t)(r * T_STRIDE + q * 16);
    asm volatile("cp.async.cg.shared.global [%0], [%1], 16;" :: "r"(sp), "l"(gp) : "memory");
}

// one 32-K chunk, 128-row A: 3 terms
__device__ __forceinline__ void mma_chunk(uint32_t tAh, uint32_t tAl, uint32_t tBh, uint32_t tBl,
                                          float acc[4][4][4],
                                          int arow, int brow, uint32_t acol0, uint32_t bcol0)
{
    #pragma unroll
    for (int kk = 0; kk < 2; kk++) {
        uint32_t ah[4][4], al[4][4], bh[4][2], bl[4][2];
        const uint32_t ka = (uint32_t)(kk * 32) + acol0;
        const uint32_t kb = (uint32_t)(kk * 32) + bcol0;
        #pragma unroll
        for (int mf = 0; mf < 4; mf++) {
            uint32_t ad = (uint32_t)(arow + mf * 16) * T_STRIDE + ka;
            LDSM_X4(ah[mf][0], ah[mf][1], ah[mf][2], ah[mf][3], tAh + ad);
            LDSM_X4(al[mf][0], al[mf][1], al[mf][2], al[mf][3], tAl + ad);
        }
        #pragma unroll
        for (int nf2 = 0; nf2 < 2; nf2++) {
            uint32_t bd = (uint32_t)(brow + nf2 * 16) * T_STRIDE + kb;
            uint32_t r0, r1, r2, r3;
            LDSM_X4(r0, r1, r2, r3, tBh + bd);
            bh[nf2 * 2][0] = r0; bh[nf2 * 2][1] = r1;
            bh[nf2 * 2 + 1][0] = r2; bh[nf2 * 2 + 1][1] = r3;
            LDSM_X4(r0, r1, r2, r3, tBl + bd);
            bl[nf2 * 2][0] = r0; bl[nf2 * 2][1] = r1;
            bl[nf2 * 2 + 1][0] = r2; bl[nf2 * 2 + 1][1] = r3;
        }
        #pragma unroll
        for (int mf = 0; mf < 4; mf++)
            #pragma unroll
            for (int nf = 0; nf < 4; nf++) {
                MMA_BF16(acc[mf][nf], ah[mf], bh[nf]);
                MMA_BF16(acc[mf][nf], ah[mf], bl[nf]);
                MMA_BF16(acc[mf][nf], al[mf], bh[nf]);
            }
    }
}

// one 32-K chunk, 64-row A (2 m-frags): 3 terms
__device__ __forceinline__ void mma_chunk64(uint32_t tAh, uint32_t tAl, uint32_t tBh, uint32_t tBl,
                                            float acc[2][4][4],
                                            int arow, int brow, uint32_t acol0, uint32_t bcol0)
{
    #pragma unroll
    for (int kk = 0; kk < 2; kk++) {
        uint32_t ah[2][4], al[2][4], bh[4][2], bl[4][2];
        const uint32_t ka = (uint32_t)(kk * 32) + acol0;
        const uint32_t kb = (uint32_t)(kk * 32) + bcol0;
        #pragma unroll
        for (int mf = 0; mf < 2; mf++) {
            uint32_t ad = (uint32_t)(arow + mf * 16) * T_STRIDE + ka;
            LDSM_X4(ah[mf][0], ah[mf][1], ah[mf][2], ah[mf][3], tAh + ad);
            LDSM_X4(al[mf][0], al[mf][1], al[mf][2], al[mf][3], tAl + ad);
        }
        #pragma unroll
        for (int nf2 = 0; nf2 < 2; nf2++) {
            uint32_t bd = (uint32_t)(brow + nf2 * 16) * T_STRIDE + kb;
            uint32_t r0, r1, r2, r3;
            LDSM_X4(r0, r1, r2, r3, tBh + bd);
            bh[nf2 * 2][0] = r0; bh[nf2 * 2][1] = r1;
            bh[nf2 * 2 + 1][0] = r2; bh[nf2 * 2 + 1][1] = r3;
            LDSM_X4(r0, r1, r2, r3, tBl + bd);
            bl[nf2 * 2][0] = r0; bl[nf2 * 2][1] = r1;
            bl[nf2 * 2 + 1][0] = r2; bl[nf2 * 2 + 1][1] = r3;
        }
        #pragma unroll
        for (int mf = 0; mf < 2; mf++)
            #pragma unroll
            for (int nf = 0; nf < 4; nf++) {
                MMA_BF16(acc[mf][nf], ah[mf], bh[nf]);
                MMA_BF16(acc[mf][nf], ah[mf], bl[nf]);
                MMA_BF16(acc[mf][nf], al[mf], bh[nf]);
            }
    }
}

// ---------------------------------------------------------------------------
// Streamed GEMM (128x128 out): 3-stage cp.async ring, one sync/chunk.
// ---------------------------------------------------------------------------
__device__ __forceinline__ void gemm_stream(
    const __nv_bfloat16* __restrict__ Ah, const __nv_bfloat16* __restrict__ Al, int ldA,
    const __nv_bfloat16* __restrict__ Bh, const __nv_bfloat16* __restrict__ Bl, int ldB,
    int nk, float acc[4][4][4], uint32_t base, int tid,
    int arow, int brow, uint32_t acol0, uint32_t bcol0)
{
    __syncthreads();
    #pragma unroll
    for (int s = 0; s < 2; s++) {
        uint32_t st = base + (uint32_t)(s * 4 * T_BYTES);
        casync_tile(st,               Ah + s * 32, ldA, tid);
        casync_tile(st + T_BYTES,     Al + s * 32, ldA, tid);
        casync_tile(st + 2 * T_BYTES, Bh + s * 32, ldB, tid);
        casync_tile(st + 3 * T_BYTES, Bl + s * 32, ldB, tid);
        CP_COMMIT();
    }
    for (int ks = 0; ks < nk; ks++) {
        if (ks < nk - 1) CP_WAIT(1); else CP_WAIT(0);
        __syncthreads();
        if (ks + 2 < nk) {
            uint32_t st = base + (uint32_t)(((ks + 2) % 3) * 4 * T_BYTES);
            casync_tile(st,               Ah + (ks + 2) * 32, ldA, tid);
            casync_tile(st + T_BYTES,     Al + (ks + 2) * 32, ldA, tid);
            casync_tile(st + 2 * T_BYTES, Bh + (ks + 2) * 32, ldB, tid);
            casync_tile(st + 3 * T_BYTES, Bl + (ks + 2) * 32, ldB, tid);
            CP_COMMIT();
        }
        uint32_t st = base + (uint32_t)((ks % 3) * 4 * T_BYTES);
        mma_chunk(st, st + T_BYTES, st + 2 * T_BYTES, st + 3 * T_BYTES,
                  acc, arow, brow, acol0, bcol0);
    }
}

// ---------------------------------------------------------------------------
// A-resident 64-row GEMM (attn): B streamed through 3-stage ring. nk=4.
// ---------------------------------------------------------------------------
__device__ __forceinline__ void gemm_ares64(
    uint32_t aTiles,
    const __nv_bfloat16* __restrict__ Bh, const __nv_bfloat16* __restrict__ Bl, int ldB,
    uint32_t stg, float acc[2][4][4], int tid,
    int arow, int brow, uint32_t acol0, uint32_t bcol0)
{
    __syncthreads();
    #pragma unroll
    for (int s = 0; s < 2; s++) {
        uint32_t st = stg + (uint32_t)(s * 2 * T_BYTES);
        casync_tile(st,           Bh + s * 32, ldB, tid);
        casync_tile(st + T_BYTES, Bl + s * 32, ldB, tid);
        CP_COMMIT();
    }
    #pragma unroll
    for (int kc = 0; kc < 4; kc++) {
        if (kc < 3) CP_WAIT(1); else CP_WAIT(0);
        __syncthreads();
        if (kc + 2 < 4) {
            uint32_t st = stg + (uint32_t)(((kc + 2) % 3) * 2 * T_BYTES);
            casync_tile(st,           Bh + (kc + 2) * 32, ldB, tid);
            casync_tile(st + T_BYTES, Bl + (kc + 2) * 32, ldB, tid);
            CP_COMMIT();
        }
        uint32_t sb = stg + (uint32_t)((kc % 3) * 2 * T_BYTES);
        mma_chunk64(aTiles + (uint32_t)(kc * 2) * T64_BYTES,
                    aTiles + (uint32_t)(kc * 2 + 1) * T64_BYTES,
                    sb, sb + T_BYTES, acc, arow, brow, acol0, bcol0);
    }
}

// 128-row fragment geometry (proj / wy)
#define FRAG_SETUP() \
    const int lane = threadIdx.x & 31, wid = threadIdx.x >> 5; \
    const int warp_m = wid >> 2, warp_n = wid & 3; \
    const int g = lane >> 2, t2 = (lane & 3) * 2; \
    (void)warp_m; (void)warp_n; (void)g; (void)t2
#define FROW(mf, h) (warp_m * 64 + (mf) * 16 + g + (h) * 8)
#define FCOL(nf)    (warp_n * 32 + (nf) * 8 + t2)
#define GEOM_SETUP() \
    const int arow = warp_m * 64 + (lane & 15); \
    const int brow = warp_n * 32 + (lane & 7) + ((lane >> 4) << 3); \
    const uint32_t acol0 = (uint32_t)((lane >> 4) << 4); \
    const uint32_t bcol0 = (uint32_t)(((lane >> 3) & 1) << 4)

// 64-row geometry (attn): warps 2(m) x 4(n), each 32x32
#define FROW64(mf, h) (warp_m * 32 + (mf) * 16 + g + (h) * 8)
#define GEOM64_SETUP() \
    const int warp_m = wid >> 2; (void)warp_m; \
    const int arow = warp_m * 32 + (lane & 15); \
    const int brow = warp_n * 32 + (lane & 7) + ((lane >> 4) << 3); \
    const uint32_t acol0 = (uint32_t)((lane >> 4) << 4); \
    const uint32_t bcol0 = (uint32_t)(((lane >> 3) & 1) << 4)

// ---------------------------------------------------------------------------
// Transpose + split x
// ---------------------------------------------------------------------------
__global__ void k_xt(const float* __restrict__ x)
{
    __shared__ float t[32][33];
    const int b = blockIdx.z, c0 = blockIdx.y * 32, n0 = blockIdx.x * 32;
    const int tx = threadIdx.x, ty = threadIdx.y;
    const float* src = x + ((size_t)b * C_IN + c0) * NN + n0;
    #pragma unroll
    for (int i = 0; i < 32; i += 8) t[ty + i][tx] = src[(size_t)(ty + i) * NN + tx];
    __syncthreads();
    #pragma unroll
    for (int i = 0; i < 32; i += 8) {
        __nv_bfloat16 h, l;
        split1(t[tx][ty + i], h, l);
        d_xTh[b][n0 + ty + i][c0 + tx] = h;
        d_xTl[b][n0 + ty + i][c0 + tx] = l;
    }
}

// ---------------------------------------------------------------------------
// Convert weights to bf16 planes
// ---------------------------------------------------------------------------
__global__ void k_wconv(const float* __restrict__ wth, const float* __restrict__ wph,
                        const float* __restrict__ wg,  const float* __restrict__ ww)
{
    int i = blockIdx.x * 256 + threadIdx.x;
    const float* src; __nv_bfloat16 *dh, *dl; int off;
    if (i < 32768)       { src = wth; dh = &d_wthh[0][0]; dl = &d_wthl[0][0]; off = i; }
    else if (i < 65536)  { src = wph; dh = &d_wphh[0][0]; dl = &d_wphl[0][0]; off = i - 32768; }
    else if (i < 98304)  { src = wg;  dh = &d_wgh[0][0];  dl = &d_wgl[0][0];  off = i - 65536; }
    else                 { src = ww;  dh = &d_wwh[0][0];  dl = &d_wwl[0][0];  off = i - 98304; }
    __nv_bfloat16 h, l;
    split1(src[off], h, l);
    dh[off] = h; dl[off] = l;
}

// ---------------------------------------------------------------------------
// Projections
// ---------------------------------------------------------------------------
__global__ __launch_bounds__(256) void k_proj(
    const float* __restrict__ b_theta, const float* __restrict__ b_phi,
    const float* __restrict__ b_g)
{
    extern __shared__ char dsm[];
    const uint32_t base = (smem_u32(dsm) + 127u) & ~127u;
    const int b  = blockIdx.z;
    const int nT = blockIdx.x * 128;
    const __nv_bfloat16 *Wh, *Wl; const float* Bp;
    if (blockIdx.y == 0)      { Wh = &d_wthh[0][0]; Wl = &d_wthl[0][0]; Bp = b_theta; }
    else if (blockIdx.y == 1) { Wh = &d_wphh[0][0]; Wl = &d_wphl[0][0]; Bp = b_phi;   }
    else                      { Wh = &d_wgh[0][0];  Wl = &d_wgl[0][0];  Bp = b_g;     }

    FRAG_SETUP();
    GEOM_SETUP();
    const int tid = threadIdx.x;
    float acc[4][4][4] = {};
    gemm_stream(&d_xTh[b][nT][0], &d_xTl[b][nT][0], C_IN, Wh, Wl, C_IN,
                C_IN / 32, acc, base, tid, arow, brow, acol0, bcol0);

    if (blockIdx.y == 0) {
        #pragma unroll
        for (int mf = 0; mf < 4; mf++)
            #pragma unroll
            for (int nf = 0; nf < 4; nf++) {
                int col = FCOL(nf);
                float2 bias = *(const float2*)&Bp[col];
                int r0 = FROW(mf, 0), r1 = FROW(mf, 1);
                uint32_t lo, hi;
                hi = pack2(acc[mf][nf][0] + bias.x, acc[mf][nf][1] + bias.y, lo);
                *(uint32_t*)&d_thh[b][nT + r0][col] = hi;
                *(uint32_t*)&d_thl[b][nT + r0][col] = lo;
                hi = pack2(acc[mf][nf][2] + bias.x, acc[mf][nf][3] + bias.y, lo);
                *(uint32_t*)&d_thh[b][nT + r1][col] = hi;
                *(uint32_t*)&d_thl[b][nT + r1][col] = lo;
            }
    } else {
        float* stg = (float*)dsm;
        __syncthreads();
        #pragma unroll
        for (int mf = 0; mf < 4; mf++)
            #pragma unroll
            for (int nf = 0; nf < 4; nf++) {
                int col = FCOL(nf);
                int r0 = FROW(mf, 0), r1 = FROW(mf, 1);
                stg[col * STG_LD + r0]       = acc[mf][nf][0];
                stg[(col + 1) * STG_LD + r0] = acc[mf][nf][1];
                stg[col * STG_LD + r1]       = acc[mf][nf][2];
                stg[(col + 1) * STG_LD + r1] = acc[mf][nf][3];
            }
        __syncthreads();
        const int m0 = blockIdx.x * 32;
        const int t = threadIdx.x;
        if (blockIdx.y == 1) {
            #pragma unroll
            for (int ob = 0; ob < 4; ob++) {
                int oo = ob * 32 + (t & 31);
                #pragma unroll
                for (int i = 0; i < 4; i++) {
                    int wp = (t >> 5) + i * 8;
                    float2 a = *(const float2*)&stg[oo * STG_LD + 2 * wp];
                    float2 c = *(const float2*)&stg[oo * STG_LD + 64 + 2 * wp];
                    float v = fmaxf(fmaxf(a.x, a.y), fmaxf(c.x, c.y)) + Bp[oo];
                    __nv_bfloat16 h, l;
                    split1(v, h, l);
                    d_phh[b][m0 + wp][oo] = h;
                    d_phl[b][m0 + wp][oo] = l;
                }
            }
        } else {
            const int wp = t & 31;
            #pragma unroll
            for (int i = 0; i < 16; i++) {
                int o = (t >> 5) + i * 8;
                float2 a = *(const float2*)&stg[o * STG_LD + 2 * wp];
                float2 c = *(const float2*)&stg[o * STG_LD + 64 + 2 * wp];
                float v = fmaxf(fmaxf(a.x, a.y), fmaxf(c.x, c.y)) + Bp[o];
                __nv_bfloat16 h, l;
                split1(v, h, l);
                d_gh[b][o][m0 + wp] = h;
                d_gl[b][o][m0 + wp] = l;
            }
        }
    }
}

// ---------------------------------------------------------------------------
// Fused attention, 64-row n-tile. smem: [thA 40960][P 40960][Bstg 61440][red 1024]
// ---------------------------------------------------------------------------
#define ATTN_THA   0
#define ATTN_P     (8 * T64_BYTES)
#define ATTN_BSTG  (ATTN_P + 8 * T64_BYTES)
#define ATTN_RED   (ATTN_BSTG + 3 * 2 * T_BYTES)
#define DSM_ATTN   (ATTN_RED + 1024 + 128)

__global__ __launch_bounds__(256) void k_attn()
{
    extern __shared__ char dsm[];
    char* dsma = (char*)((((uintptr_t)dsm) + 127) & ~(uintptr_t)127);
    const uint32_t base = smem_u32(dsma);
    const uint32_t thA  = base + ATTN_THA;
    const uint32_t Pb   = base + ATTN_P;
    const uint32_t Bstg = base + ATTN_BSTG;
    float* redbuf = (float*)(dsma + ATTN_RED);

    const int b  = blockIdx.z;
    const int nT = blockIdx.x * 64;
    const int tid = threadIdx.x;
    const int lane = tid & 31, wid = tid >> 5;
    const int warp_n = wid & 3;
    const int g = lane >> 2, t2 = (lane & 3) * 2;
    GEOM64_SETUP();

    // load theta tile (64 rows x 128 K, hi/lo) once
    {
        const __nv_bfloat16* Ah = &d_thh[b][nT][0];
        const __nv_bfloat16* Al = &d_thl[b][nT][0];
        #pragma unroll
        for (int kc = 0; kc < 4; kc++) {
            casync_tile64(thA + (uint32_t)(kc * 2) * T64_BYTES,     Ah + kc * 32, C_I, tid);
            casync_tile64(thA + (uint32_t)(kc * 2 + 1) * T64_BYTES, Al + kc * 32, C_I, tid);
        }
        CP_COMMIT();
        CP_WAIT(0);
        __syncthreads();
    }

    float yacc[2][4][4] = {};
    float ps[2][2] = {};

    for (int mt = 0; mt < 8; mt++) {
        const int mT = mt * 128;

        // phase A: scores (64 x 128)
        float facc[2][4][4] = {};
        gemm_ares64(thA, &d_phh[b][mT][0], &d_phl[b][mT][0], C_I,
                    Bstg, facc, tid, arow, brow, acol0, bcol0);

        // phase B: exp + row partials + P -> smem (warp_n owns m-chunk warp_n)
        const uint32_t Ph = Pb + (uint32_t)(warp_n * 2) * T64_BYTES;
        const uint32_t Pl = Ph + T64_BYTES;
        #pragma unroll
        for (int mf = 0; mf < 2; mf++) {
            const int r0 = FROW64(mf, 0), r1 = FROW64(mf, 1);
            #pragma unroll
            for (int nf = 0; nf < 4; nf++) {
                float e0 = __expf(facc[mf][nf][0]);
                float e1 = __expf(facc[mf][nf][1]);
                float e2 = __expf(facc[mf][nf][2]);
                float e3 = __expf(facc[mf][nf][3]);
                ps[mf][0] += e0 + e1;
                ps[mf][1] += e2 + e3;
                uint32_t lo0, lo1;
                uint32_t hi0 = pack2(e0, e1, lo0);
                uint32_t hi1 = pack2(e2, e3, lo1);
                uint32_t off0 = (uint32_t)(r0 * T_STRIDE + (nf * 8 + t2) * 2);
                uint32_t off1 = (uint32_t)(r1 * T_STRIDE + (nf * 8 + t2) * 2);
                asm volatile("st.shared.b32 [%0], %1;" :: "r"(Ph + off0), "r"(hi0));
                asm volatile("st.shared.b32 [%0], %1;" :: "r"(Pl + off0), "r"(lo0));
                asm volatile("st.shared.b32 [%0], %1;" :: "r"(Ph + off1), "r"(hi1));
                asm volatile("st.shared.b32 [%0], %1;" :: "r"(Pl + off1), "r"(lo1));
            }
        }

        // phase C: yacc += P · g^T
        gemm_ares64(Pb, &d_gh[b][0][mT], &d_gl[b][0][mT], MM,
                    Bstg, yacc, tid, arow, brow, acol0, bcol0);
    }

    // epilogue: cross-warp row sums, normalize, write y planes
    #pragma unroll
    for (int mf = 0; mf < 2; mf++)
        #pragma unroll
        for (int h = 0; h < 2; h++) {
            float v = ps[mf][h];
            v += __shfl_xor_sync(0xffffffffu, v, 1);
            v += __shfl_xor_sync(0xffffffffu, v, 2);
            if ((lane & 3) == 0) redbuf[warp_n * 64 + FROW64(mf, h)] = v;
        }
    __syncthreads();
    #pragma unroll
    for (int mf = 0; mf < 2; mf++)
        #pragma unroll
        for (int h = 0; h < 2; h++) {
            int row = FROW64(mf, h);
            float iv = 1.f / (redbuf[row] + redbuf[64 + row] +
                              redbuf[128 + row] + redbuf[192 + row]);
            #pragma unroll
            for (int nf = 0; nf < 4; nf++) {
                float c0 = yacc[mf][nf][2 * h]     * iv;
                float c1 = yacc[mf][nf][2 * h + 1] * iv;
                uint32_t lo, hi = pack2(c0, c1, lo);
                *(uint32_t*)&d_yh[b][nT + row][FCOL(nf)] = hi;
                *(uint32_t*)&d_yl[b][nT + row][FCOL(nf)] = lo;
            }
        }
}

// ---------------------------------------------------------------------------
// wy
// ---------------------------------------------------------------------------
__global__ __launch_bounds__(256) void k_wy(const float* __restrict__ b_w)
{
    extern __shared__ char dsm[];
    const uint32_t base = (smem_u32(dsm) + 127u) & ~127u;
    const int b  = blockIdx.z;
    const int cT = blockIdx.y * 128;
    const int nT = blockIdx.x * 128;

    FRAG_SETUP();
    GEOM_SETUP();
    const int tid = threadIdx.x;
    float acc[4][4][4] = {};
    gemm_stream(&d_wwh[cT][0], &d_wwl[cT][0], C_I,
                &d_yh[b][nT][0], &d_yl[b][nT][0], C_I,
                C_I / 32, acc, base, tid, arow, brow, acol0, bcol0);

    const int sub = blockIdx.x * 4 + warp_n;
    #pragma unroll
    for (int mf = 0; mf < 4; mf++)
        #pragma unroll
        for (int h = 0; h < 2; h++) {
            int row = FROW(mf, h);
            int c = cT + row;
            float bias = b_w[c];
            float s = 0.f, ss = 0.f;
            #pragma unroll
            for (int nf = 0; nf < 4; nf++) {
                float c0 = acc[mf][nf][2 * h]     + bias;
                float c1 = acc[mf][nf][2 * h + 1] + bias;
                s += c0 + c1;
                ss += c0 * c0 + c1 * c1;
                *(float2*)&d_wy[b][c][nT + FCOL(nf)] = make_float2(c0, c1);
            }
            s  += __shfl_xor_sync(0xffffffffu, s, 1);
            s  += __shfl_xor_sync(0xffffffffu, s, 2);
            ss += __shfl_xor_sync(0xffffffffu, ss, 1);
            ss += __shfl_xor_sync(0xffffffffu, ss, 2);
            if ((lane & 3) == 0) { d_bns[b][c][sub] = s; d_bnss[b][c][sub] = ss; }
        }
}

// ---------------------------------------------------------------------------
// BN finalize
// ---------------------------------------------------------------------------
__global__ void k_bnfin(const float* __restrict__ gamma, const float* __restrict__ beta)
{
    const int c = blockIdx.x;
    const int t = threadIdx.x;
    float s = 0.f, ss = 0.f;
    #pragma unroll
    for (int i = 0; i < 4; i++) {
        int id = t + i * 256;
        int b = id >> 7, tile = id & 127;
        s  += d_bns [b][c][tile];
        ss += d_bnss[b][c][tile];
    }
    const int lane = t & 31, warp = t >> 5;
    #pragma unroll
    for (int o = 16; o > 0; o >>= 1) {
        s  += __shfl_xor_sync(0xffffffffu, s, o);
        ss += __shfl_xor_sync(0xffffffffu, ss, o);
    }
    __shared__ float rs[8], rss[8];
    if (lane == 0) { rs[warp] = s; rss[warp] = ss; }
    __syncthreads();
    if (t == 0) {
        float S = 0.f, SS = 0.f;
        #pragma unroll
        for (int i = 0; i < 8; i++) { S += rs[i]; SS += rss[i]; }
        const float invN = 1.f / (BATCH * NN);
        float mean = S * invN;
        float var  = SS * invN - mean * mean;
        float istd = rsqrtf(var + 1e-5f);
        float sc = gamma[c] * istd;
        d_scale[c] = sc;
        d_shift[c] = beta[c] - mean * sc;
    }
}

// ---------------------------------------------------------------------------
// out = BN(wy) + x
// ---------------------------------------------------------------------------
__global__ void k_final(const float* __restrict__ x, float* __restrict__ out)
{
    size_t i4 = (size_t)blockIdx.x * blockDim.x + threadIdx.x;
    if (i4 >= (size_t)BATCH * C_IN * NN / 4) return;
    int c = (int)((i4 >> 10) & (C_IN - 1));
    float sc = d_scale[c], sh = d_shift[c];
    float4 w  = ((const float4*)&d_wy[0][0][0])[i4];
    float4 xv = ((const float4*)x)[i4];
    float4 o;
    o.x = w.x * sc + sh + xv.x;
    o.y = w.y * sc + sh + xv.y;
    o.z = w.z * sc + sh + xv.z;
    o.w = w.w * sc + sh + xv.w;
    ((float4*)out)[i4] = o;
}

// ---------------------------------------------------------------------------
extern "C" void kernel_launch(void* const* d_in, const int* in_sizes, int n_in,
                              void* d_out, int out_size)
{
    const float* x       = (const float*)d_in[0];
    const float* w_g     = (const float*)d_in[1];
    const float* b_g     = (const float*)d_in[2];
    const float* w_theta = (const float*)d_in[3];
    const float* b_theta = (const float*)d_in[4];
    const float* w_phi   = (const float*)d_in[5];
    const float* b_phi   = (const float*)d_in[6];
    const float* w_w     = (const float*)d_in[7];
    const float* b_w     = (const float*)d_in[8];
    const float* gamma   = (const float*)d_in[9];
    const float* beta    = (const float*)d_in[10];
    float* out = (float*)d_out;

    cudaFuncSetAttribute(k_proj, cudaFuncAttributeMaxDynamicSharedMemorySize, DSM_GEMM);
    cudaFuncSetAttribute(k_attn, cudaFuncAttributeMaxDynamicSharedMemorySize, DSM_ATTN);
    cudaFuncSetAttribute(k_wy,   cudaFuncAttributeMaxDynamicSharedMemorySize, DSM_GEMM);

    k_xt   <<<dim3(NN / 32, C_IN / 32, BATCH), dim3(32, 8)>>>(x);
    k_wconv<<<512, 256>>>(w_theta, w_phi, w_g, w_w);
    k_proj <<<dim3(32, 3, BATCH), 256, DSM_GEMM>>>(b_theta, b_phi, b_g);
    k_attn <<<dim3(64, 1, BATCH), 256, DSM_ATTN>>>();
    k_wy   <<<dim3(32, 2, BATCH), 256, DSM_GEMM>>>(b_w);
    k_bnfin<<<C_IN, 256>>>(gamma, beta);
    k_final<<<(BATCH * C_IN * NN / 4 + 255) / 256, 256>>>(x, out);
}

// round 9
// speedup vs baseline: 1.1419x; 1.1419x over previous
#include <cuda_runtime.h>
#include <cuda_bf16.h>
#include <math.h>
#include <stdint.h>

#define BATCH 8
#define C_IN 256
#define C_I  128
#define NN   4096
#define MM   1024

// ---------------------------------------------------------------------------
// Scratch: bf16 hi/lo operand planes + fp32 outputs
// ---------------------------------------------------------------------------
__device__ __align__(16) __nv_bfloat16 d_xTh[BATCH][NN][C_IN];
__device__ __align__(16) __nv_bfloat16 d_xTl[BATCH][NN][C_IN];
__device__ __align__(16) __nv_bfloat16 d_thh[BATCH][NN][C_I];
__device__ __align__(16) __nv_bfloat16 d_thl[BATCH][NN][C_I];
__device__ __align__(16) __nv_bfloat16 d_phh[BATCH][MM][C_I];
__device__ __align__(16) __nv_bfloat16 d_phl[BATCH][MM][C_I];
__device__ __align__(16) __nv_bfloat16 d_gh [BATCH][C_I][MM];
__device__ __align__(16) __nv_bfloat16 d_gl [BATCH][C_I][MM];
__device__ __align__(16) __nv_bfloat16 d_yh [BATCH][NN][C_I];
__device__ __align__(16) __nv_bfloat16 d_yl [BATCH][NN][C_I];
__device__ __align__(16) __nv_bfloat16 d_wthh[C_I][C_IN], d_wthl[C_I][C_IN];
__device__ __align__(16) __nv_bfloat16 d_wphh[C_I][C_IN], d_wphl[C_I][C_IN];
__device__ __align__(16) __nv_bfloat16 d_wgh [C_I][C_IN], d_wgl [C_I][C_IN];
__device__ __align__(16) __nv_bfloat16 d_wwh [C_IN][C_I], d_wwl [C_IN][C_I];

__device__ float d_wy [BATCH][C_IN][NN];
__device__ float d_bns [BATCH][C_IN][128];
__device__ float d_bnss[BATCH][C_IN][128];
__device__ float d_scale[C_IN];
__device__ float d_shift[C_IN];

// ---------------------------------------------------------------------------
// helpers
// ---------------------------------------------------------------------------
__device__ __forceinline__ uint32_t smem_u32(const void* p) {
    uint32_t a;
    asm("{ .reg .u64 t; cvta.to.shared.u64 t, %1; cvt.u32.u64 %0, t; }" : "=r"(a) : "l"(p));
    return a;
}

#define LDSM_X4(r0, r1, r2, r3, addr) \
    asm volatile("ldmatrix.sync.aligned.m8n8.x4.shared.b16 {%0,%1,%2,%3}, [%4];" \
        : "=r"(r0), "=r"(r1), "=r"(r2), "=r"(r3) : "r"(addr))

#define MMA_BF16(c, a, b) \
    asm volatile("mma.sync.aligned.m16n8k16.row.col.f32.bf16.bf16.f32 " \
        "{%0,%1,%2,%3}, {%4,%5,%6,%7}, {%8,%9}, {%0,%1,%2,%3};" \
        : "+f"((c)[0]), "+f"((c)[1]), "+f"((c)[2]), "+f"((c)[3]) \
        : "r"((a)[0]), "r"((a)[1]), "r"((a)[2]), "r"((a)[3]), "r"((b)[0]), "r"((b)[1]))

#define CP_COMMIT()  asm volatile("cp.async.commit_group;" ::: "memory")
#define CP_WAIT(n)   asm volatile("cp.async.wait_group %0;" :: "n"(n) : "memory")

__device__ __forceinline__ uint32_t pack2(float a, float b, uint32_t& lo)
{
    __nv_bfloat16 ha = __float2bfloat16(a), hb = __float2bfloat16(b);
    __nv_bfloat16 la = __float2bfloat16(a - __bfloat162float(ha));
    __nv_bfloat16 lb = __float2bfloat16(b - __bfloat162float(hb));
    lo = ((uint32_t)__bfloat16_as_ushort(lb) << 16) | __bfloat16_as_ushort(la);
    return ((uint32_t)__bfloat16_as_ushort(hb) << 16) | __bfloat16_as_ushort(ha);
}

__device__ __forceinline__ void split1(float v, __nv_bfloat16& h, __nv_bfloat16& l)
{
    h = __float2bfloat16(v);
    l = __float2bfloat16(v - __bfloat162float(h));
}

#define T_STRIDE 80
#define T_BYTES  (128 * T_STRIDE)            // 10240 (128-row tile)
#define DSM_GEMM (3 * 4 * T_BYTES + 128)
#define STG_LD   132

// async copy one 128x32 bf16 tile with 256 threads (2 x 16B per thread)
__device__ __forceinline__ void casync_tile(uint32_t dst, const __nv_bfloat16* __restrict__ src,
                                            int ld, int tid)
{
    #pragma unroll
    for (int i = 0; i < 2; i++) {
        int c = tid * 2 + i;
        int r = c >> 2, q = c & 3;
        const __nv_bfloat16* gp = src + (size_t)r * ld + q * 8;
        uint32_t sp = dst + (uint32_t)(r * T_STRIDE + q * 16);
        asm volatile("cp.async.cg.shared.global [%0], [%1], 16;" :: "r"(sp), "l"(gp) : "memory");
    }
}

// async copy one 128x32 bf16 tile with 512 threads (1 x 16B per thread)
__device__ __forceinline__ void casync_tile512(uint32_t dst, const __nv_bfloat16* __restrict__ src,
                                               int ld, int tid)
{
    int r = tid >> 2, q = tid & 3;
    const __nv_bfloat16* gp = src + (size_t)r * ld + q * 8;
    uint32_t sp = dst + (uint32_t)(r * T_STRIDE + q * 16);
    asm volatile("cp.async.cg.shared.global [%0], [%1], 16;" :: "r"(sp), "l"(gp) : "memory");
}

// one 32-K chunk, 4 m-frags (proj / wy, 256 threads)
__device__ __forceinline__ void mma_chunk(uint32_t tAh, uint32_t tAl, uint32_t tBh, uint32_t tBl,
                                          float acc[4][4][4],
                                          int arow, int brow, uint32_t acol0, uint32_t bcol0)
{
    #pragma unroll
    for (int kk = 0; kk < 2; kk++) {
        uint32_t ah[4][4], al[4][4], bh[4][2], bl[4][2];
        const uint32_t ka = (uint32_t)(kk * 32) + acol0;
        const uint32_t kb = (uint32_t)(kk * 32) + bcol0;
        #pragma unroll
        for (int mf = 0; mf < 4; mf++) {
            uint32_t ad = (uint32_t)(arow + mf * 16) * T_STRIDE + ka;
            LDSM_X4(ah[mf][0], ah[mf][1], ah[mf][2], ah[mf][3], tAh + ad);
            LDSM_X4(al[mf][0], al[mf][1], al[mf][2], al[mf][3], tAl + ad);
        }
        #pragma unroll
        for (int nf2 = 0; nf2 < 2; nf2++) {
            uint32_t bd = (uint32_t)(brow + nf2 * 16) * T_STRIDE + kb;
            uint32_t r0, r1, r2, r3;
            LDSM_X4(r0, r1, r2, r3, tBh + bd);
            bh[nf2 * 2][0] = r0; bh[nf2 * 2][1] = r1;
            bh[nf2 * 2 + 1][0] = r2; bh[nf2 * 2 + 1][1] = r3;
            LDSM_X4(r0, r1, r2, r3, tBl + bd);
            bl[nf2 * 2][0] = r0; bl[nf2 * 2][1] = r1;
            bl[nf2 * 2 + 1][0] = r2; bl[nf2 * 2 + 1][1] = r3;
        }
        #pragma unroll
        for (int mf = 0; mf < 4; mf++)
            #pragma unroll
            for (int nf = 0; nf < 4; nf++) {
                MMA_BF16(acc[mf][nf], ah[mf], bh[nf]);
                MMA_BF16(acc[mf][nf], ah[mf], bl[nf]);
                MMA_BF16(acc[mf][nf], al[mf], bh[nf]);
            }
    }
}

// one 32-K chunk, 2 m-frags (attn, 512 threads)
__device__ __forceinline__ void mma_chunk2(uint32_t tAh, uint32_t tAl, uint32_t tBh, uint32_t tBl,
                                           float acc[2][4][4],
                                           int arow, int brow, uint32_t acol0, uint32_t bcol0)
{
    #pragma unroll
    for (int kk = 0; kk < 2; kk++) {
        uint32_t ah[2][4], al[2][4], bh[4][2], bl[4][2];
        const uint32_t ka = (uint32_t)(kk * 32) + acol0;
        const uint32_t kb = (uint32_t)(kk * 32) + bcol0;
        #pragma unroll
        for (int mf = 0; mf < 2; mf++) {
            uint32_t ad = (uint32_t)(arow + mf * 16) * T_STRIDE + ka;
            LDSM_X4(ah[mf][0], ah[mf][1], ah[mf][2], ah[mf][3], tAh + ad);
            LDSM_X4(al[mf][0], al[mf][1], al[mf][2], al[mf][3], tAl + ad);
        }
        #pragma unroll
        for (int nf2 = 0; nf2 < 2; nf2++) {
            uint32_t bd = (uint32_t)(brow + nf2 * 16) * T_STRIDE + kb;
            uint32_t r0, r1, r2, r3;
            LDSM_X4(r0, r1, r2, r3, tBh + bd);
            bh[nf2 * 2][0] = r0; bh[nf2 * 2][1] = r1;
            bh[nf2 * 2 + 1][0] = r2; bh[nf2 * 2 + 1][1] = r3;
            LDSM_X4(r0, r1, r2, r3, tBl + bd);
            bl[nf2 * 2][0] = r0; bl[nf2 * 2][1] = r1;
            bl[nf2 * 2 + 1][0] = r2; bl[nf2 * 2 + 1][1] = r3;
        }
        #pragma unroll
        for (int mf = 0; mf < 2; mf++)
            #pragma unroll
            for (int nf = 0; nf < 4; nf++) {
                MMA_BF16(acc[mf][nf], ah[mf], bh[nf]);
                MMA_BF16(acc[mf][nf], ah[mf], bl[nf]);
                MMA_BF16(acc[mf][nf], al[mf], bh[nf]);
            }
    }
}

// ---------------------------------------------------------------------------
// Streamed GEMM (128x128 out, 256 threads): 3-stage cp.async ring.
// ---------------------------------------------------------------------------
__device__ __forceinline__ void gemm_stream(
    const __nv_bfloat16* __restrict__ Ah, const __nv_bfloat16* __restrict__ Al, int ldA,
    const __nv_bfloat16* __restrict__ Bh, const __nv_bfloat16* __restrict__ Bl, int ldB,
    int nk, float acc[4][4][4], uint32_t base, int tid,
    int arow, int brow, uint32_t acol0, uint32_t bcol0)
{
    __syncthreads();
    #pragma unroll
    for (int s = 0; s < 2; s++) {
        uint32_t st = base + (uint32_t)(s * 4 * T_BYTES);
        casync_tile(st,               Ah + s * 32, ldA, tid);
        casync_tile(st + T_BYTES,     Al + s * 32, ldA, tid);
        casync_tile(st + 2 * T_BYTES, Bh + s * 32, ldB, tid);
        casync_tile(st + 3 * T_BYTES, Bl + s * 32, ldB, tid);
        CP_COMMIT();
    }
    for (int ks = 0; ks < nk; ks++) {
        if (ks < nk - 1) CP_WAIT(1); else CP_WAIT(0);
        __syncthreads();
        if (ks + 2 < nk) {
            uint32_t st = base + (uint32_t)(((ks + 2) % 3) * 4 * T_BYTES);
            casync_tile(st,               Ah + (ks + 2) * 32, ldA, tid);
            casync_tile(st + T_BYTES,     Al + (ks + 2) * 32, ldA, tid);
            casync_tile(st + 2 * T_BYTES, Bh + (ks + 2) * 32, ldB, tid);
            casync_tile(st + 3 * T_BYTES, Bl + (ks + 2) * 32, ldB, tid);
            CP_COMMIT();
        }
        uint32_t st = base + (uint32_t)((ks % 3) * 4 * T_BYTES);
        mma_chunk(st, st + T_BYTES, st + 2 * T_BYTES, st + 3 * T_BYTES,
                  acc, arow, brow, acol0, bcol0);
    }
}

// ---------------------------------------------------------------------------
// A-resident GEMM (attn, 512 threads): B streamed via 3-stage ring. nk=4.
// ---------------------------------------------------------------------------
__device__ __forceinline__ void gemm_ares512(
    uint32_t aTiles,
    const __nv_bfloat16* __restrict__ Bh, const __nv_bfloat16* __restrict__ Bl, int ldB,
    uint32_t stg, float acc[2][4][4], int tid,
    int arow, int brow, uint32_t acol0, uint32_t bcol0)
{
    __syncthreads();
    #pragma unroll
    for (int s = 0; s < 2; s++) {
        uint32_t st = stg + (uint32_t)(s * 2 * T_BYTES);
        casync_tile512(st,           Bh + s * 32, ldB, tid);
        casync_tile512(st + T_BYTES, Bl + s * 32, ldB, tid);
        CP_COMMIT();
    }
    #pragma unroll
    for (int kc = 0; kc < 4; kc++) {
        if (kc < 3) CP_WAIT(1); else CP_WAIT(0);
        __syncthreads();
        if (kc + 2 < 4) {
            uint32_t st = stg + (uint32_t)(((kc + 2) % 3) * 2 * T_BYTES);
            casync_tile512(st,           Bh + (kc + 2) * 32, ldB, tid);
            casync_tile512(st + T_BYTES, Bl + (kc + 2) * 32, ldB, tid);
            CP_COMMIT();
        }
        uint32_t sb = stg + (uint32_t)((kc % 3) * 2 * T_BYTES);
        mma_chunk2(aTiles + (uint32_t)(kc * 2) * T_BYTES,
                   aTiles + (uint32_t)(kc * 2 + 1) * T_BYTES,
                   sb, sb + T_BYTES, acc, arow, brow, acol0, bcol0);
    }
}

// 128-row fragment geometry (proj / wy; 8 warps 2x4)
#define FRAG_SETUP() \
    const int lane = threadIdx.x & 31, wid = threadIdx.x >> 5; \
    const int warp_m = wid >> 2, warp_n = wid & 3; \
    const int g = lane >> 2, t2 = (lane & 3) * 2; \
    (void)warp_m; (void)warp_n; (void)g; (void)t2
#define FROW(mf, h) (warp_m * 64 + (mf) * 16 + g + (h) * 8)
#define FCOL(nf)    (warp_n * 32 + (nf) * 8 + t2)
#define GEOM_SETUP() \
    const int arow = warp_m * 64 + (lane & 15); \
    const int brow = warp_n * 32 + (lane & 7) + ((lane >> 4) << 3); \
    const uint32_t acol0 = (uint32_t)((lane >> 4) << 4); \
    const uint32_t bcol0 = (uint32_t)(((lane >> 3) & 1) << 4)

// attn geometry (16 warps 4x4, 32x32 per warp)
#define FROW32(mf, h) (warp_m * 32 + (mf) * 16 + g + (h) * 8)

// ---------------------------------------------------------------------------
// Transpose + split x
// ---------------------------------------------------------------------------
__global__ void k_xt(const float* __restrict__ x)
{
    __shared__ float t[32][33];
    const int b = blockIdx.z, c0 = blockIdx.y * 32, n0 = blockIdx.x * 32;
    const int tx = threadIdx.x, ty = threadIdx.y;
    const float* src = x + ((size_t)b * C_IN + c0) * NN + n0;
    #pragma unroll
    for (int i = 0; i < 32; i += 8) t[ty + i][tx] = src[(size_t)(ty + i) * NN + tx];
    __syncthreads();
    #pragma unroll
    for (int i = 0; i < 32; i += 8) {
        __nv_bfloat16 h, l;
        split1(t[tx][ty + i], h, l);
        d_xTh[b][n0 + ty + i][c0 + tx] = h;
        d_xTl[b][n0 + ty + i][c0 + tx] = l;
    }
}

// ---------------------------------------------------------------------------
// Convert weights to bf16 planes
// ---------------------------------------------------------------------------
__global__ void k_wconv(const float* __restrict__ wth, const float* __restrict__ wph,
                        const float* __restrict__ wg,  const float* __restrict__ ww)
{
    int i = blockIdx.x * 256 + threadIdx.x;
    const float* src; __nv_bfloat16 *dh, *dl; int off;
    if (i < 32768)       { src = wth; dh = &d_wthh[0][0]; dl = &d_wthl[0][0]; off = i; }
    else if (i < 65536)  { src = wph; dh = &d_wphh[0][0]; dl = &d_wphl[0][0]; off = i - 32768; }
    else if (i < 98304)  { src = wg;  dh = &d_wgh[0][0];  dl = &d_wgl[0][0];  off = i - 65536; }
    else                 { src = ww;  dh = &d_wwh[0][0];  dl = &d_wwl[0][0];  off = i - 98304; }
    __nv_bfloat16 h, l;
    split1(src[off], h, l);
    dh[off] = h; dl[off] = l;
}

// ---------------------------------------------------------------------------
// Projections
// ---------------------------------------------------------------------------
__global__ __launch_bounds__(256) void k_proj(
    const float* __restrict__ b_theta, const float* __restrict__ b_phi,
    const float* __restrict__ b_g)
{
    extern __shared__ char dsm[];
    const uint32_t base = (smem_u32(dsm) + 127u) & ~127u;
    const int b  = blockIdx.z;
    const int nT = blockIdx.x * 128;
    const __nv_bfloat16 *Wh, *Wl; const float* Bp;
    if (blockIdx.y == 0)      { Wh = &d_wthh[0][0]; Wl = &d_wthl[0][0]; Bp = b_theta; }
    else if (blockIdx.y == 1) { Wh = &d_wphh[0][0]; Wl = &d_wphl[0][0]; Bp = b_phi;   }
    else                      { Wh = &d_wgh[0][0];  Wl = &d_wgl[0][0];  Bp = b_g;     }

    FRAG_SETUP();
    GEOM_SETUP();
    const int tid = threadIdx.x;
    float acc[4][4][4] = {};
    gemm_stream(&d_xTh[b][nT][0], &d_xTl[b][nT][0], C_IN, Wh, Wl, C_IN,
                C_IN / 32, acc, base, tid, arow, brow, acol0, bcol0);

    if (blockIdx.y == 0) {
        #pragma unroll
        for (int mf = 0; mf < 4; mf++)
            #pragma unroll
            for (int nf = 0; nf < 4; nf++) {
                int col = FCOL(nf);
                float2 bias = *(const float2*)&Bp[col];
                int r0 = FROW(mf, 0), r1 = FROW(mf, 1);
                uint32_t lo, hi;
                hi = pack2(acc[mf][nf][0] + bias.x, acc[mf][nf][1] + bias.y, lo);
                *(uint32_t*)&d_thh[b][nT + r0][col] = hi;
                *(uint32_t*)&d_thl[b][nT + r0][col] = lo;
                hi = pack2(acc[mf][nf][2] + bias.x, acc[mf][nf][3] + bias.y, lo);
                *(uint32_t*)&d_thh[b][nT + r1][col] = hi;
                *(uint32_t*)&d_thl[b][nT + r1][col] = lo;
            }
    } else {
        float* stg = (float*)dsm;
        __syncthreads();
        #pragma unroll
        for (int mf = 0; mf < 4; mf++)
            #pragma unroll
            for (int nf = 0; nf < 4; nf++) {
                int col = FCOL(nf);
                int r0 = FROW(mf, 0), r1 = FROW(mf, 1);
                stg[col * STG_LD + r0]       = acc[mf][nf][0];
                stg[(col + 1) * STG_LD + r0] = acc[mf][nf][1];
                stg[col * STG_LD + r1]       = acc[mf][nf][2];
                stg[(col + 1) * STG_LD + r1] = acc[mf][nf][3];
            }
        __syncthreads();
        const int m0 = blockIdx.x * 32;
        const int t = threadIdx.x;
        if (blockIdx.y == 1) {
            #pragma unroll
            for (int ob = 0; ob < 4; ob++) {
                int oo = ob * 32 + (t & 31);
                #pragma unroll
                for (int i = 0; i < 4; i++) {
                    int wp = (t >> 5) + i * 8;
                    float2 a = *(const float2*)&stg[oo * STG_LD + 2 * wp];
                    float2 c = *(const float2*)&stg[oo * STG_LD + 64 + 2 * wp];
                    float v = fmaxf(fmaxf(a.x, a.y), fmaxf(c.x, c.y)) + Bp[oo];
                    __nv_bfloat16 h, l;
                    split1(v, h, l);
                    d_phh[b][m0 + wp][oo] = h;
                    d_phl[b][m0 + wp][oo] = l;
                }
            }
        } else {
            const int wp = t & 31;
            #pragma unroll
            for (int i = 0; i < 16; i++) {
                int o = (t >> 5) + i * 8;
                float2 a = *(const float2*)&stg[o * STG_LD + 2 * wp];
                float2 c = *(const float2*)&stg[o * STG_LD + 64 + 2 * wp];
                float v = fmaxf(fmaxf(a.x, a.y), fmaxf(c.x, c.y)) + Bp[o];
                __nv_bfloat16 h, l;
                split1(v, h, l);
                d_gh[b][o][m0 + wp] = h;
                d_gl[b][o][m0 + wp] = l;
            }
        }
    }
}

// ---------------------------------------------------------------------------
// Fused attention, 128-row n-tile, 512 threads (4x4 warps, 32x32/warp).
// smem: [thA 81920][P 81920][Bstg 61440][red 2048]
// ---------------------------------------------------------------------------
#define ATTN_THA   0
#define ATTN_P     (8 * T_BYTES)
#define ATTN_BSTG  (ATTN_P + 8 * T_BYTES)
#define ATTN_RED   (ATTN_BSTG + 3 * 2 * T_BYTES)
#define DSM_ATTN   (ATTN_RED + 2048 + 128)

__global__ __launch_bounds__(512) void k_attn()
{
    extern __shared__ char dsm[];
    char* dsma = (char*)((((uintptr_t)dsm) + 127) & ~(uintptr_t)127);
    const uint32_t base = smem_u32(dsma);
    const uint32_t thA  = base + ATTN_THA;
    const uint32_t Pb   = base + ATTN_P;
    const uint32_t Bstg = base + ATTN_BSTG;
    float* redbuf = (float*)(dsma + ATTN_RED);

    const int b  = blockIdx.z;
    const int nT = blockIdx.x * 128;
    const int tid = threadIdx.x;
    const int lane = tid & 31, wid = tid >> 5;
    const int warp_m = wid >> 2, warp_n = wid & 3;
    const int g = lane >> 2, t2 = (lane & 3) * 2;
    const int arow = warp_m * 32 + (lane & 15);
    const int brow = warp_n * 32 + (lane & 7) + ((lane >> 4) << 3);
    const uint32_t acol0 = (uint32_t)((lane >> 4) << 4);
    const uint32_t bcol0 = (uint32_t)(((lane >> 3) & 1) << 4);

    // load theta tile (128 rows x 128 K, hi/lo) once
    {
        const __nv_bfloat16* Ah = &d_thh[b][nT][0];
        const __nv_bfloat16* Al = &d_thl[b][nT][0];
        #pragma unroll
        for (int kc = 0; kc < 4; kc++) {
            casync_tile512(thA + (uint32_t)(kc * 2) * T_BYTES,     Ah + kc * 32, C_I, tid);
            casync_tile512(thA + (uint32_t)(kc * 2 + 1) * T_BYTES, Al + kc * 32, C_I, tid);
        }
        CP_COMMIT();
        CP_WAIT(0);
        __syncthreads();
    }

    float yacc[2][4][4] = {};
    float ps[2][2] = {};

    for (int mt = 0; mt < 8; mt++) {
        const int mT = mt * 128;

        // phase A: scores (128 x 128)
        float facc[2][4][4] = {};
        gemm_ares512(thA, &d_phh[b][mT][0], &d_phl[b][mT][0], C_I,
                     Bstg, facc, tid, arow, brow, acol0, bcol0);

        // phase B: exp + row partials + P -> smem (warp_n owns K-chunk warp_n)
        const uint32_t Ph = Pb + (uint32_t)(warp_n * 2) * T_BYTES;
        const uint32_t Pl = Ph + T_BYTES;
        #pragma unroll
        for (int mf = 0; mf < 2; mf++) {
            const int r0 = FROW32(mf, 0), r1 = FROW32(mf, 1);
            #pragma unroll
            for (int nf = 0; nf < 4; nf++) {
                float e0 = __expf(facc[mf][nf][0]);
                float e1 = __expf(facc[mf][nf][1]);
                float e2 = __expf(facc[mf][nf][2]);
                float e3 = __expf(facc[mf][nf][3]);
                ps[mf][0] += e0 + e1;
                ps[mf][1] += e2 + e3;
                uint32_t lo0, lo1;
                uint32_t hi0 = pack2(e0, e1, lo0);
                uint32_t hi1 = pack2(e2, e3, lo1);
                uint32_t off0 = (uint32_t)(r0 * T_STRIDE + (nf * 8 + t2) * 2);
                uint32_t off1 = (uint32_t)(r1 * T_STRIDE + (nf * 8 + t2) * 2);
                asm volatile("st.shared.b32 [%0], %1;" :: "r"(Ph + off0), "r"(hi0));
                asm volatile("st.shared.b32 [%0], %1;" :: "r"(Pl + off0), "r"(lo0));
                asm volatile("st.shared.b32 [%0], %1;" :: "r"(Ph + off1), "r"(hi1));
                asm volatile("st.shared.b32 [%0], %1;" :: "r"(Pl + off1), "r"(lo1));
            }
        }

        // phase C: yacc += P · g^T
        gemm_ares512(Pb, &d_gh[b][0][mT], &d_gl[b][0][mT], MM,
                     Bstg, yacc, tid, arow, brow, acol0, bcol0);
    }

    // epilogue: cross-warp row sums, normalize, write y planes
    #pragma unroll
    for (int mf = 0; mf < 2; mf++)
        #pragma unroll
        for (int h = 0; h < 2; h++) {
            float v = ps[mf][h];
            v += __shfl_xor_sync(0xffffffffu, v, 1);
            v += __shfl_xor_sync(0xffffffffu, v, 2);
            if ((lane & 3) == 0) redbuf[warp_n * 128 + FROW32(mf, h)] = v;
        }
    __syncthreads();
    #pragma unroll
    for (int mf = 0; mf < 2; mf++)
        #pragma unroll
        for (int h = 0; h < 2; h++) {
            int row = FROW32(mf, h);
            float iv = 1.f / (redbuf[row] + redbuf[128 + row] +
                              redbuf[256 + row] + redbuf[384 + row]);
            #pragma unroll
            for (int nf = 0; nf < 4; nf++) {
                float c0 = yacc[mf][nf][2 * h]     * iv;
                float c1 = yacc[mf][nf][2 * h + 1] * iv;
                uint32_t lo, hi = pack2(c0, c1, lo);
                *(uint32_t*)&d_yh[b][nT + row][warp_n * 32 + nf * 8 + t2] = hi;
                *(uint32_t*)&d_yl[b][nT + row][warp_n * 32 + nf * 8 + t2] = lo;
            }
        }
}

// ---------------------------------------------------------------------------
// wy
// ---------------------------------------------------------------------------
__global__ __launch_bounds__(256) void k_wy(const float* __restrict__ b_w)
{
    extern __shared__ char dsm[];
    const uint32_t base = (smem_u32(dsm) + 127u) & ~127u;
    const int b  = blockIdx.z;
    const int cT = blockIdx.y * 128;
    const int nT = blockIdx.x * 128;

    FRAG_SETUP();
    GEOM_SETUP();
    const int tid = threadIdx.x;
    float acc[4][4][4] = {};
    gemm_stream(&d_wwh[cT][0], &d_wwl[cT][0], C_I,
                &d_yh[b][nT][0], &d_yl[b][nT][0], C_I,
                C_I / 32, acc, base, tid, arow, brow, acol0, bcol0);

    const int sub = blockIdx.x * 4 + warp_n;
    #pragma unroll
    for (int mf = 0; mf < 4; mf++)
        #pragma unroll
        for (int h = 0; h < 2; h++) {
            int row = FROW(mf, h);
            int c = cT + row;
            float bias = b_w[c];
            float s = 0.f, ss = 0.f;
            #pragma unroll
            for (int nf = 0; nf < 4; nf++) {
                float c0 = acc[mf][nf][2 * h]     + bias;
                float c1 = acc[mf][nf][2 * h + 1] + bias;
                s += c0 + c1;
                ss += c0 * c0 + c1 * c1;
                *(float2*)&d_wy[b][c][nT + FCOL(nf)] = make_float2(c0, c1);
            }
            s  += __shfl_xor_sync(0xffffffffu, s, 1);
            s  += __shfl_xor_sync(0xffffffffu, s, 2);
            ss += __shfl_xor_sync(0xffffffffu, ss, 1);
            ss += __shfl_xor_sync(0xffffffffu, ss, 2);
            if ((lane & 3) == 0) { d_bns[b][c][sub] = s; d_bnss[b][c][sub] = ss; }
        }
}

// ---------------------------------------------------------------------------
// BN finalize
// ---------------------------------------------------------------------------
__global__ void k_bnfin(const float* __restrict__ gamma, const float* __restrict__ beta)
{
    const int c = blockIdx.x;
    const int t = threadIdx.x;
    float s = 0.f, ss = 0.f;
    #pragma unroll
    for (int i = 0; i < 4; i++) {
        int id = t + i * 256;
        int b = id >> 7, tile = id & 127;
        s  += d_bns [b][c][tile];
        ss += d_bnss[b][c][tile];
    }
    const int lane = t & 31, warp = t >> 5;
    #pragma unroll
    for (int o = 16; o > 0; o >>= 1) {
        s  += __shfl_xor_sync(0xffffffffu, s, o);
        ss += __shfl_xor_sync(0xffffffffu, ss, o);
    }
    __shared__ float rs[8], rss[8];
    if (lane == 0) { rs[warp] = s; rss[warp] = ss; }
    __syncthreads();
    if (t == 0) {
        float S = 0.f, SS = 0.f;
        #pragma unroll
        for (int i = 0; i < 8; i++) { S += rs[i]; SS += rss[i]; }
        const float invN = 1.f / (BATCH * NN);
        float mean = S * invN;
        float var  = SS * invN - mean * mean;
        float istd = rsqrtf(var + 1e-5f);
        float sc = gamma[c] * istd;
        d_scale[c] = sc;
        d_shift[c] = beta[c] - mean * sc;
    }
}

// ---------------------------------------------------------------------------
// out = BN(wy) + x
// ---------------------------------------------------------------------------
__global__ void k_final(const float* __restrict__ x, float* __restrict__ out)
{
    size_t i4 = (size_t)blockIdx.x * blockDim.x + threadIdx.x;
    if (i4 >= (size_t)BATCH * C_IN * NN / 4) return;
    int c = (int)((i4 >> 10) & (C_IN - 1));
    float sc = d_scale[c], sh = d_shift[c];
    float4 w  = ((const float4*)&d_wy[0][0][0])[i4];
    float4 xv = ((const float4*)x)[i4];
    float4 o;
    o.x = w.x * sc + sh + xv.x;
    o.y = w.y * sc + sh + xv.y;
    o.z = w.z * sc + sh + xv.z;
    o.w = w.w * sc + sh + xv.w;
    ((float4*)out)[i4] = o;
}

// ---------------------------------------------------------------------------
extern "C" void kernel_launch(void* const* d_in, const int* in_sizes, int n_in,
                              void* d_out, int out_size)
{
    const float* x       = (const float*)d_in[0];
    const float* w_g     = (const float*)d_in[1];
    const float* b_g     = (const float*)d_in[2];
    const float* w_theta = (const float*)d_in[3];
    const float* b_theta = (const float*)d_in[4];
    const float* w_phi   = (const float*)d_in[5];
    const float* b_phi   = (const float*)d_in[6];
    const float* w_w     = (const float*)d_in[7];
    const float* b_w     = (const float*)d_in[8];
    const float* gamma   = (const float*)d_in[9];
    const float* beta    = (const float*)d_in[10];
    float* out = (float*)d_out;

    cudaFuncSetAttribute(k_proj, cudaFuncAttributeMaxDynamicSharedMemorySize, DSM_GEMM);
    cudaFuncSetAttribute(k_attn, cudaFuncAttributeMaxDynamicSharedMemorySize, DSM_ATTN);
    cudaFuncSetAttribute(k_wy,   cudaFuncAttributeMaxDynamicSharedMemorySize, DSM_GEMM);

    k_xt   <<<dim3(NN / 32, C_IN / 32, BATCH), dim3(32, 8)>>>(x);
    k_wconv<<<512, 256>>>(w_theta, w_phi, w_g, w_w);
    k_proj <<<dim3(32, 3, BATCH), 256, DSM_GEMM>>>(b_theta, b_phi, b_g);
    k_attn <<<dim3(32, 1, BATCH), 512, DSM_ATTN>>>();
    k_wy   <<<dim3(32, 2, BATCH), 256, DSM_GEMM>>>(b_w);
    k_bnfin<<<C_IN, 256>>>(gamma, beta);
    k_final<<<(BATCH * C_IN * NN / 4 + 255) / 256, 256>>>(x, out);
}

// round 10
// speedup vs baseline: 1.3115x; 1.1485x over previous
#include <cuda_runtime.h>
#include <cuda_bf16.h>
#include <cuda_fp16.h>
#include <math.h>
#include <stdint.h>

#define BATCH 8
#define C_IN 256
#define C_I  128
#define NN   4096
#define MM   1024

// ---------------------------------------------------------------------------
// Scratch: operand planes + fp32 outputs
// x / weights / y: bf16 hi+lo (3-term GEMMs).  theta: fp16 hi+lo.  phi,g: fp16 single.
// ---------------------------------------------------------------------------
__device__ __align__(16) __nv_bfloat16 d_xTh[BATCH][NN][C_IN];
__device__ __align__(16) __nv_bfloat16 d_xTl[BATCH][NN][C_IN];
__device__ __align__(16) __half        d_thh[BATCH][NN][C_I];
__device__ __align__(16) __half        d_thl[BATCH][NN][C_I];
__device__ __align__(16) __half        d_phh[BATCH][MM][C_I];   // phi single fp16
__device__ __align__(16) __half        d_gh [BATCH][C_I][MM];   // g single fp16
__device__ __align__(16) __nv_bfloat16 d_yh [BATCH][NN][C_I];
__device__ __align__(16) __nv_bfloat16 d_yl [BATCH][NN][C_I];
__device__ __align__(16) __nv_bfloat16 d_wthh[C_I][C_IN], d_wthl[C_I][C_IN];
__device__ __align__(16) __nv_bfloat16 d_wphh[C_I][C_IN], d_wphl[C_I][C_IN];
__device__ __align__(16) __nv_bfloat16 d_wgh [C_I][C_IN], d_wgl [C_I][C_IN];
__device__ __align__(16) __nv_bfloat16 d_wwh [C_IN][C_I], d_wwl [C_IN][C_I];

__device__ float d_wy [BATCH][C_IN][NN];
__device__ float d_bns [BATCH][C_IN][128];
__device__ float d_bnss[BATCH][C_IN][128];
__device__ float d_scale[C_IN];
__device__ float d_shift[C_IN];

// ---------------------------------------------------------------------------
// helpers
// ---------------------------------------------------------------------------
__device__ __forceinline__ uint32_t smem_u32(const void* p) {
    uint32_t a;
    asm("{ .reg .u64 t; cvta.to.shared.u64 t, %1; cvt.u32.u64 %0, t; }" : "=r"(a) : "l"(p));
    return a;
}

#define LDSM_X4(r0, r1, r2, r3, addr) \
    asm volatile("ldmatrix.sync.aligned.m8n8.x4.shared.b16 {%0,%1,%2,%3}, [%4];" \
        : "=r"(r0), "=r"(r1), "=r"(r2), "=r"(r3) : "r"(addr))

#define MMA_BF16(c, a, b) \
    asm volatile("mma.sync.aligned.m16n8k16.row.col.f32.bf16.bf16.f32 " \
        "{%0,%1,%2,%3}, {%4,%5,%6,%7}, {%8,%9}, {%0,%1,%2,%3};" \
        : "+f"((c)[0]), "+f"((c)[1]), "+f"((c)[2]), "+f"((c)[3]) \
        : "r"((a)[0]), "r"((a)[1]), "r"((a)[2]), "r"((a)[3]), "r"((b)[0]), "r"((b)[1]))

#define MMA_FP16(c, a, b) \
    asm volatile("mma.sync.aligned.m16n8k16.row.col.f32.f16.f16.f32 " \
        "{%0,%1,%2,%3}, {%4,%5,%6,%7}, {%8,%9}, {%0,%1,%2,%3};" \
        : "+f"((c)[0]), "+f"((c)[1]), "+f"((c)[2]), "+f"((c)[3]) \
        : "r"((a)[0]), "r"((a)[1]), "r"((a)[2]), "r"((a)[3]), "r"((b)[0]), "r"((b)[1]))

#define CP_COMMIT()  asm volatile("cp.async.commit_group;" ::: "memory")
#define CP_WAIT(n)   asm volatile("cp.async.wait_group %0;" :: "n"(n) : "memory")

// bf16 hi/lo pair pack
__device__ __forceinline__ uint32_t pack2(float a, float b, uint32_t& lo)
{
    __nv_bfloat16 ha = __float2bfloat16(a), hb = __float2bfloat16(b);
    __nv_bfloat16 la = __float2bfloat16(a - __bfloat162float(ha));
    __nv_bfloat16 lb = __float2bfloat16(b - __bfloat162float(hb));
    lo = ((uint32_t)__bfloat16_as_ushort(lb) << 16) | __bfloat16_as_ushort(la);
    return ((uint32_t)__bfloat16_as_ushort(hb) << 16) | __bfloat16_as_ushort(ha);
}

// fp16 hi/lo pair pack
__device__ __forceinline__ uint32_t pack2h(float a, float b, uint32_t& lo)
{
    __half ha = __float2half_rn(a), hb = __float2half_rn(b);
    __half la = __float2half_rn(a - __half2float(ha));
    __half lb = __float2half_rn(b - __half2float(hb));
    lo = ((uint32_t)__half_as_ushort(lb) << 16) | __half_as_ushort(la);
    return ((uint32_t)__half_as_ushort(hb) << 16) | __half_as_ushort(ha);
}

__device__ __forceinline__ void split1(float v, __nv_bfloat16& h, __nv_bfloat16& l)
{
    h = __float2bfloat16(v);
    l = __float2bfloat16(v - __bfloat162float(h));
}

__device__ __forceinline__ void split1h(float v, __half& h, __half& l)
{
    h = __float2half_rn(v);
    l = __float2half_rn(v - __half2float(h));
}

#define T_STRIDE 80
#define T_BYTES  (128 * T_STRIDE)            // 10240 (128-row tile)
#define DSM_GEMM (3 * 4 * T_BYTES + 128)
#define STG_LD   132

// async copy one 128x32 16-bit tile with 256 threads (2 x 16B per thread)
__device__ __forceinline__ void casync_tile(uint32_t dst, const uint16_t* __restrict__ src,
                                            int ld, int tid)
{
    #pragma unroll
    for (int i = 0; i < 2; i++) {
        int c = tid * 2 + i;
        int r = c >> 2, q = c & 3;
        const uint16_t* gp = src + (size_t)r * ld + q * 8;
        uint32_t sp = dst + (uint32_t)(r * T_STRIDE + q * 16);
        asm volatile("cp.async.cg.shared.global [%0], [%1], 16;" :: "r"(sp), "l"(gp) : "memory");
    }
}

// async copy one 128x32 16-bit tile with 512 threads (1 x 16B per thread)
__device__ __forceinline__ void casync_tile512(uint32_t dst, const uint16_t* __restrict__ src,
                                               int ld, int tid)
{
    int r = tid >> 2, q = tid & 3;
    const uint16_t* gp = src + (size_t)r * ld + q * 8;
    uint32_t sp = dst + (uint32_t)(r * T_STRIDE + q * 16);
    asm volatile("cp.async.cg.shared.global [%0], [%1], 16;" :: "r"(sp), "l"(gp) : "memory");
}

// one 32-K chunk, 4 m-frags, bf16 3-term (proj / wy, 256 threads)
__device__ __forceinline__ void mma_chunk(uint32_t tAh, uint32_t tAl, uint32_t tBh, uint32_t tBl,
                                          float acc[4][4][4],
                                          int arow, int brow, uint32_t acol0, uint32_t bcol0)
{
    #pragma unroll
    for (int kk = 0; kk < 2; kk++) {
        uint32_t ah[4][4], al[4][4], bh[4][2], bl[4][2];
        const uint32_t ka = (uint32_t)(kk * 32) + acol0;
        const uint32_t kb = (uint32_t)(kk * 32) + bcol0;
        #pragma unroll
        for (int mf = 0; mf < 4; mf++) {
            uint32_t ad = (uint32_t)(arow + mf * 16) * T_STRIDE + ka;
            LDSM_X4(ah[mf][0], ah[mf][1], ah[mf][2], ah[mf][3], tAh + ad);
            LDSM_X4(al[mf][0], al[mf][1], al[mf][2], al[mf][3], tAl + ad);
        }
        #pragma unroll
        for (int nf2 = 0; nf2 < 2; nf2++) {
            uint32_t bd = (uint32_t)(brow + nf2 * 16) * T_STRIDE + kb;
            uint32_t r0, r1, r2, r3;
            LDSM_X4(r0, r1, r2, r3, tBh + bd);
            bh[nf2 * 2][0] = r0; bh[nf2 * 2][1] = r1;
            bh[nf2 * 2 + 1][0] = r2; bh[nf2 * 2 + 1][1] = r3;
            LDSM_X4(r0, r1, r2, r3, tBl + bd);
            bl[nf2 * 2][0] = r0; bl[nf2 * 2][1] = r1;
            bl[nf2 * 2 + 1][0] = r2; bl[nf2 * 2 + 1][1] = r3;
        }
        #pragma unroll
        for (int mf = 0; mf < 4; mf++)
            #pragma unroll
            for (int nf = 0; nf < 4; nf++) {
                MMA_BF16(acc[mf][nf], ah[mf], bh[nf]);
                MMA_BF16(acc[mf][nf], ah[mf], bl[nf]);
                MMA_BF16(acc[mf][nf], al[mf], bh[nf]);
            }
    }
}

// one 32-K chunk, 2 m-frags, fp16 2-term: A hi/lo resident, B single plane (attn)
__device__ __forceinline__ void mma_chunk2h(uint32_t tAh, uint32_t tAl, uint32_t tB,
                                            float acc[2][4][4],
                                            int arow, int brow, uint32_t acol0, uint32_t bcol0)
{
    #pragma unroll
    for (int kk = 0; kk < 2; kk++) {
        uint32_t ah[2][4], al[2][4], bf[4][2];
        const uint32_t ka = (uint32_t)(kk * 32) + acol0;
        const uint32_t kb = (uint32_t)(kk * 32) + bcol0;
        #pragma unroll
        for (int mf = 0; mf < 2; mf++) {
            uint32_t ad = (uint32_t)(arow + mf * 16) * T_STRIDE + ka;
            LDSM_X4(ah[mf][0], ah[mf][1], ah[mf][2], ah[mf][3], tAh + ad);
            LDSM_X4(al[mf][0], al[mf][1], al[mf][2], al[mf][3], tAl + ad);
        }
        #pragma unroll
        for (int nf2 = 0; nf2 < 2; nf2++) {
            uint32_t bd = (uint32_t)(brow + nf2 * 16) * T_STRIDE + kb;
            uint32_t r0, r1, r2, r3;
            LDSM_X4(r0, r1, r2, r3, tB + bd);
            bf[nf2 * 2][0] = r0; bf[nf2 * 2][1] = r1;
            bf[nf2 * 2 + 1][0] = r2; bf[nf2 * 2 + 1][1] = r3;
        }
        #pragma unroll
        for (int mf = 0; mf < 2; mf++)
            #pragma unroll
            for (int nf = 0; nf < 4; nf++) {
                MMA_FP16(acc[mf][nf], ah[mf], bf[nf]);
                MMA_FP16(acc[mf][nf], al[mf], bf[nf]);
            }
    }
}

// ---------------------------------------------------------------------------
// Streamed GEMM (128x128 out, 256 threads, bf16 3-term): 3-stage cp.async ring.
// ---------------------------------------------------------------------------
__device__ __forceinline__ void gemm_stream(
    const __nv_bfloat16* __restrict__ Ah, const __nv_bfloat16* __restrict__ Al, int ldA,
    const __nv_bfloat16* __restrict__ Bh, const __nv_bfloat16* __restrict__ Bl, int ldB,
    int nk, float acc[4][4][4], uint32_t base, int tid,
    int arow, int brow, uint32_t acol0, uint32_t bcol0)
{
    __syncthreads();
    #pragma unroll
    for (int s = 0; s < 2; s++) {
        uint32_t st = base + (uint32_t)(s * 4 * T_BYTES);
        casync_tile(st,               (const uint16_t*)(Ah + s * 32), ldA, tid);
        casync_tile(st + T_BYTES,     (const uint16_t*)(Al + s * 32), ldA, tid);
        casync_tile(st + 2 * T_BYTES, (const uint16_t*)(Bh + s * 32), ldB, tid);
        casync_tile(st + 3 * T_BYTES, (const uint16_t*)(Bl + s * 32), ldB, tid);
        CP_COMMIT();
    }
    for (int ks = 0; ks < nk; ks++) {
        if (ks < nk - 1) CP_WAIT(1); else CP_WAIT(0);
        __syncthreads();
        if (ks + 2 < nk) {
            uint32_t st = base + (uint32_t)(((ks + 2) % 3) * 4 * T_BYTES);
            casync_tile(st,               (const uint16_t*)(Ah + (ks + 2) * 32), ldA, tid);
            casync_tile(st + T_BYTES,     (const uint16_t*)(Al + (ks + 2) * 32), ldA, tid);
            casync_tile(st + 2 * T_BYTES, (const uint16_t*)(Bh + (ks + 2) * 32), ldB, tid);
            casync_tile(st + 3 * T_BYTES, (const uint16_t*)(Bl + (ks + 2) * 32), ldB, tid);
            CP_COMMIT();
        }
        uint32_t st = base + (uint32_t)((ks % 3) * 4 * T_BYTES);
        mma_chunk(st, st + T_BYTES, st + 2 * T_BYTES, st + 3 * T_BYTES,
                  acc, arow, brow, acol0, bcol0);
    }
}

// ---------------------------------------------------------------------------
// A-resident fp16 2-term GEMM (attn, 512 threads): single-plane B streamed,
// 3-stage x 1-tile ring. nk=4.
// ---------------------------------------------------------------------------
__device__ __forceinline__ void gemm_ares512h(
    uint32_t aTiles, const uint16_t* __restrict__ B, int ldB,
    uint32_t stg, float acc[2][4][4], int tid,
    int arow, int brow, uint32_t acol0, uint32_t bcol0)
{
    __syncthreads();
    #pragma unroll
    for (int s = 0; s < 2; s++) {
        casync_tile512(stg + (uint32_t)(s * T_BYTES), B + s * 32, ldB, tid);
        CP_COMMIT();
    }
    #pragma unroll
    for (int kc = 0; kc < 4; kc++) {
        if (kc < 3) CP_WAIT(1); else CP_WAIT(0);
        __syncthreads();
        if (kc + 2 < 4) {
            casync_tile512(stg + (uint32_t)(((kc + 2) % 3) * T_BYTES), B + (kc + 2) * 32, ldB, tid);
            CP_COMMIT();
        }
        mma_chunk2h(aTiles + (uint32_t)(kc * 2) * T_BYTES,
                    aTiles + (uint32_t)(kc * 2 + 1) * T_BYTES,
                    stg + (uint32_t)((kc % 3) * T_BYTES),
                    acc, arow, brow, acol0, bcol0);
    }
}

// 128-row fragment geometry (proj / wy; 8 warps 2x4)
#define FRAG_SETUP() \
    const int lane = threadIdx.x & 31, wid = threadIdx.x >> 5; \
    const int warp_m = wid >> 2, warp_n = wid & 3; \
    const int g = lane >> 2, t2 = (lane & 3) * 2; \
    (void)warp_m; (void)warp_n; (void)g; (void)t2
#define FROW(mf, h) (warp_m * 64 + (mf) * 16 + g + (h) * 8)
#define FCOL(nf)    (warp_n * 32 + (nf) * 8 + t2)
#define GEOM_SETUP() \
    const int arow = warp_m * 64 + (lane & 15); \
    const int brow = warp_n * 32 + (lane & 7) + ((lane >> 4) << 3); \
    const uint32_t acol0 = (uint32_t)((lane >> 4) << 4); \
    const uint32_t bcol0 = (uint32_t)(((lane >> 3) & 1) << 4)

// attn geometry (16 warps 4x4, 32x32 per warp)
#define FROW32(mf, h) (warp_m * 32 + (mf) * 16 + g + (h) * 8)

// ---------------------------------------------------------------------------
// Transpose + split x
// ---------------------------------------------------------------------------
__global__ void k_xt(const float* __restrict__ x)
{
    __shared__ float t[32][33];
    const int b = blockIdx.z, c0 = blockIdx.y * 32, n0 = blockIdx.x * 32;
    const int tx = threadIdx.x, ty = threadIdx.y;
    const float* src = x + ((size_t)b * C_IN + c0) * NN + n0;
    #pragma unroll
    for (int i = 0; i < 32; i += 8) t[ty + i][tx] = src[(size_t)(ty + i) * NN + tx];
    __syncthreads();
    #pragma unroll
    for (int i = 0; i < 32; i += 8) {
        __nv_bfloat16 h, l;
        split1(t[tx][ty + i], h, l);
        d_xTh[b][n0 + ty + i][c0 + tx] = h;
        d_xTl[b][n0 + ty + i][c0 + tx] = l;
    }
}

// ---------------------------------------------------------------------------
// Convert weights to bf16 planes
// ---------------------------------------------------------------------------
__global__ void k_wconv(const float* __restrict__ wth, const float* __restrict__ wph,
                        const float* __restrict__ wg,  const float* __restrict__ ww)
{
    int i = blockIdx.x * 256 + threadIdx.x;
    const float* src; __nv_bfloat16 *dh, *dl; int off;
    if (i < 32768)       { src = wth; dh = &d_wthh[0][0]; dl = &d_wthl[0][0]; off = i; }
    else if (i < 65536)  { src = wph; dh = &d_wphh[0][0]; dl = &d_wphl[0][0]; off = i - 32768; }
    else if (i < 98304)  { src = wg;  dh = &d_wgh[0][0];  dl = &d_wgl[0][0];  off = i - 65536; }
    else                 { src = ww;  dh = &d_wwh[0][0];  dl = &d_wwl[0][0];  off = i - 98304; }
    __nv_bfloat16 h, l;
    split1(src[off], h, l);
    dh[off] = h; dl[off] = l;
}

// ---------------------------------------------------------------------------
// Projections: theta -> fp16 hi/lo planes; phi -> single fp16; g -> single fp16
// ---------------------------------------------------------------------------
__global__ __launch_bounds__(256) void k_proj(
    const float* __restrict__ b_theta, const float* __restrict__ b_phi,
    const float* __restrict__ b_g)
{
    extern __shared__ char dsm[];
    const uint32_t base = (smem_u32(dsm) + 127u) & ~127u;
    const int b  = blockIdx.z;
    const int nT = blockIdx.x * 128;
    const __nv_bfloat16 *Wh, *Wl; const float* Bp;
    if (blockIdx.y == 0)      { Wh = &d_wthh[0][0]; Wl = &d_wthl[0][0]; Bp = b_theta; }
    else if (blockIdx.y == 1) { Wh = &d_wphh[0][0]; Wl = &d_wphl[0][0]; Bp = b_phi;   }
    else                      { Wh = &d_wgh[0][0];  Wl = &d_wgl[0][0];  Bp = b_g;     }

    FRAG_SETUP();
    GEOM_SETUP();
    const int tid = threadIdx.x;
    float acc[4][4][4] = {};
    gemm_stream(&d_xTh[b][nT][0], &d_xTl[b][nT][0], C_IN, Wh, Wl, C_IN,
                C_IN / 32, acc, base, tid, arow, brow, acol0, bcol0);

    if (blockIdx.y == 0) {
        #pragma unroll
        for (int mf = 0; mf < 4; mf++)
            #pragma unroll
            for (int nf = 0; nf < 4; nf++) {
                int col = FCOL(nf);
                float2 bias = *(const float2*)&Bp[col];
                int r0 = FROW(mf, 0), r1 = FROW(mf, 1);
                uint32_t lo, hi;
                hi = pack2h(acc[mf][nf][0] + bias.x, acc[mf][nf][1] + bias.y, lo);
                *(uint32_t*)&d_thh[b][nT + r0][col] = hi;
                *(uint32_t*)&d_thl[b][nT + r0][col] = lo;
                hi = pack2h(acc[mf][nf][2] + bias.x, acc[mf][nf][3] + bias.y, lo);
                *(uint32_t*)&d_thh[b][nT + r1][col] = hi;
                *(uint32_t*)&d_thl[b][nT + r1][col] = lo;
            }
    } else {
        float* stg = (float*)dsm;
        __syncthreads();
        #pragma unroll
        for (int mf = 0; mf < 4; mf++)
            #pragma unroll
            for (int nf = 0; nf < 4; nf++) {
                int col = FCOL(nf);
                int r0 = FROW(mf, 0), r1 = FROW(mf, 1);
                stg[col * STG_LD + r0]       = acc[mf][nf][0];
                stg[(col + 1) * STG_LD + r0] = acc[mf][nf][1];
                stg[col * STG_LD + r1]       = acc[mf][nf][2];
                stg[(col + 1) * STG_LD + r1] = acc[mf][nf][3];
            }
        __syncthreads();
        const int m0 = blockIdx.x * 32;
        const int t = threadIdx.x;
        if (blockIdx.y == 1) {
            #pragma unroll
            for (int ob = 0; ob < 4; ob++) {
                int oo = ob * 32 + (t & 31);
                #pragma unroll
                for (int i = 0; i < 4; i++) {
                    int wp = (t >> 5) + i * 8;
                    float2 a = *(const float2*)&stg[oo * STG_LD + 2 * wp];
                    float2 c = *(const float2*)&stg[oo * STG_LD + 64 + 2 * wp];
                    float v = fmaxf(fmaxf(a.x, a.y), fmaxf(c.x, c.y)) + Bp[oo];
                    d_phh[b][m0 + wp][oo] = __float2half_rn(v);
                }
            }
        } else {
            const int wp = t & 31;
            #pragma unroll
            for (int i = 0; i < 16; i++) {
                int o = (t >> 5) + i * 8;
                float2 a = *(const float2*)&stg[o * STG_LD + 2 * wp];
                float2 c = *(const float2*)&stg[o * STG_LD + 64 + 2 * wp];
                float v = fmaxf(fmaxf(a.x, a.y), fmaxf(c.x, c.y)) + Bp[o];
                d_gh[b][o][m0 + wp] = __float2half_rn(v);
            }
        }
    }
}

// ---------------------------------------------------------------------------
// Fused attention, 128-row n-tile, 512 threads, fp16 2-term GEMMs.
// smem: [thA 81920][P 81920][Bstg 30720][red 2048]
// ---------------------------------------------------------------------------
#define ATTN_THA   0
#define ATTN_P     (8 * T_BYTES)
#define ATTN_BSTG  (ATTN_P + 8 * T_BYTES)
#define ATTN_RED   (ATTN_BSTG + 3 * T_BYTES)
#define DSM_ATTN   (ATTN_RED + 2048 + 128)

__global__ __launch_bounds__(512) void k_attn()
{
    extern __shared__ char dsm[];
    char* dsma = (char*)((((uintptr_t)dsm) + 127) & ~(uintptr_t)127);
    const uint32_t base = smem_u32(dsma);
    const uint32_t thA  = base + ATTN_THA;
    const uint32_t Pb   = base + ATTN_P;
    const uint32_t Bstg = base + ATTN_BSTG;
    float* redbuf = (float*)(dsma + ATTN_RED);

    const int b  = blockIdx.z;
    const int nT = blockIdx.x * 128;
    const int tid = threadIdx.x;
    const int lane = tid & 31, wid = tid >> 5;
    const int warp_m = wid >> 2, warp_n = wid & 3;
    const int g = lane >> 2, t2 = (lane & 3) * 2;
    const int arow = warp_m * 32 + (lane & 15);
    const int brow = warp_n * 32 + (lane & 7) + ((lane >> 4) << 3);
    const uint32_t acol0 = (uint32_t)((lane >> 4) << 4);
    const uint32_t bcol0 = (uint32_t)(((lane >> 3) & 1) << 4);

    // load theta tile (128 rows x 128 K, fp16 hi/lo) once
    {
        const uint16_t* Ah = (const uint16_t*)&d_thh[b][nT][0];
        const uint16_t* Al = (const uint16_t*)&d_thl[b][nT][0];
        #pragma unroll
        for (int kc = 0; kc < 4; kc++) {
            casync_tile512(thA + (uint32_t)(kc * 2) * T_BYTES,     Ah + kc * 32, C_I, tid);
            casync_tile512(thA + (uint32_t)(kc * 2 + 1) * T_BYTES, Al + kc * 32, C_I, tid);
        }
        CP_COMMIT();
        CP_WAIT(0);
        __syncthreads();
    }

    float yacc[2][4][4] = {};
    float ps[2][2] = {};

    for (int mt = 0; mt < 8; mt++) {
        const int mT = mt * 128;

        // phase A: scores (fp16 2-term: theta hi/lo x phi single)
        float facc[2][4][4] = {};
        gemm_ares512h(thA, (const uint16_t*)&d_phh[b][mT][0], C_I,
                      Bstg, facc, tid, arow, brow, acol0, bcol0);

        // phase B: exp + row partials + P -> smem as fp16 hi/lo (warp_n owns chunk warp_n)
        const uint32_t Ph = Pb + (uint32_t)(warp_n * 2) * T_BYTES;
        const uint32_t Pl = Ph + T_BYTES;
        #pragma unroll
        for (int mf = 0; mf < 2; mf++) {
            const int r0 = FROW32(mf, 0), r1 = FROW32(mf, 1);
            #pragma unroll
            for (int nf = 0; nf < 4; nf++) {
                float e0 = __expf(facc[mf][nf][0]);
                float e1 = __expf(facc[mf][nf][1]);
                float e2 = __expf(facc[mf][nf][2]);
                float e3 = __expf(facc[mf][nf][3]);
                ps[mf][0] += e0 + e1;
                ps[mf][1] += e2 + e3;
                uint32_t lo0, lo1;
                uint32_t hi0 = pack2h(e0, e1, lo0);
                uint32_t hi1 = pack2h(e2, e3, lo1);
                uint32_t off0 = (uint32_t)(r0 * T_STRIDE + (nf * 8 + t2) * 2);
                uint32_t off1 = (uint32_t)(r1 * T_STRIDE + (nf * 8 + t2) * 2);
                asm volatile("st.shared.b32 [%0], %1;" :: "r"(Ph + off0), "r"(hi0));
                asm volatile("st.shared.b32 [%0], %1;" :: "r"(Pl + off0), "r"(lo0));
                asm volatile("st.shared.b32 [%0], %1;" :: "r"(Ph + off1), "r"(hi1));
                asm volatile("st.shared.b32 [%0], %1;" :: "r"(Pl + off1), "r"(lo1));
            }
        }

        // phase C: yacc += P · g^T (fp16 2-term: P hi/lo x g single)
        gemm_ares512h(Pb, (const uint16_t*)&d_gh[b][0][mT], MM,
                      Bstg, yacc, tid, arow, brow, acol0, bcol0);
    }

    // epilogue: cross-warp row sums, normalize, write y planes (bf16 hi/lo)
    #pragma unroll
    for (int mf = 0; mf < 2; mf++)
        #pragma unroll
        for (int h = 0; h < 2; h++) {
            float v = ps[mf][h];
            v += __shfl_xor_sync(0xffffffffu, v, 1);
            v += __shfl_xor_sync(0xffffffffu, v, 2);
            if ((lane & 3) == 0) redbuf[warp_n * 128 + FROW32(mf, h)] = v;
        }
    __syncthreads();
    #pragma unroll
    for (int mf = 0; mf < 2; mf++)
        #pragma unroll
        for (int h = 0; h < 2; h++) {
            int row = FROW32(mf, h);
            float iv = 1.f / (redbuf[row] + redbuf[128 + row] +
                              redbuf[256 + row] + redbuf[384 + row]);
            #pragma unroll
            for (int nf = 0; nf < 4; nf++) {
                float c0 = yacc[mf][nf][2 * h]     * iv;
                float c1 = yacc[mf][nf][2 * h + 1] * iv;
                uint32_t lo, hi = pack2(c0, c1, lo);
                *(uint32_t*)&d_yh[b][nT + row][warp_n * 32 + nf * 8 + t2] = hi;
                *(uint32_t*)&d_yl[b][nT + row][warp_n * 32 + nf * 8 + t2] = lo;
            }
        }
}

// ---------------------------------------------------------------------------
// wy (bf16 3-term, unchanged)
// ---------------------------------------------------------------------------
__global__ __launch_bounds__(256) void k_wy(const float* __restrict__ b_w)
{
    extern __shared__ char dsm[];
    const uint32_t base = (smem_u32(dsm) + 127u) & ~127u;
    const int b  = blockIdx.z;
    const int cT = blockIdx.y * 128;
    const int nT = blockIdx.x * 128;

    FRAG_SETUP();
    GEOM_SETUP();
    const int tid = threadIdx.x;
    float acc[4][4][4] = {};
    gemm_stream(&d_wwh[cT][0], &d_wwl[cT][0], C_I,
                &d_yh[b][nT][0], &d_yl[b][nT][0], C_I,
                C_I / 32, acc, base, tid, arow, brow, acol0, bcol0);

    const int sub = blockIdx.x * 4 + warp_n;
    #pragma unroll
    for (int mf = 0; mf < 4; mf++)
        #pragma unroll
        for (int h = 0; h < 2; h++) {
            int row = FROW(mf, h);
            int c = cT + row;
            float bias = b_w[c];
            float s = 0.f, ss = 0.f;
            #pragma unroll
            for (int nf = 0; nf < 4; nf++) {
                float c0 = acc[mf][nf][2 * h]     + bias;
                float c1 = acc[mf][nf][2 * h + 1] + bias;
                s += c0 + c1;
                ss += c0 * c0 + c1 * c1;
                *(float2*)&d_wy[b][c][nT + FCOL(nf)] = make_float2(c0, c1);
            }
            s  += __shfl_xor_sync(0xffffffffu, s, 1);
            s  += __shfl_xor_sync(0xffffffffu, s, 2);
            ss += __shfl_xor_sync(0xffffffffu, ss, 1);
            ss += __shfl_xor_sync(0xffffffffu, ss, 2);
            if ((lane & 3) == 0) { d_bns[b][c][sub] = s; d_bnss[b][c][sub] = ss; }
        }
}

// ---------------------------------------------------------------------------
// BN finalize
// ---------------------------------------------------------------------------
__global__ void k_bnfin(const float* __restrict__ gamma, const float* __restrict__ beta)
{
    const int c = blockIdx.x;
    const int t = threadIdx.x;
    float s = 0.f, ss = 0.f;
    #pragma unroll
    for (int i = 0; i < 4; i++) {
        int id = t + i * 256;
        int b = id >> 7, tile = id & 127;
        s  += d_bns [b][c][tile];
        ss += d_bnss[b][c][tile];
    }
    const int lane = t & 31, warp = t >> 5;
    #pragma unroll
    for (int o = 16; o > 0; o >>= 1) {
        s  += __shfl_xor_sync(0xffffffffu, s, o);
        ss += __shfl_xor_sync(0xffffffffu, ss, o);
    }
    __shared__ float rs[8], rss[8];
    if (lane == 0) { rs[warp] = s; rss[warp] = ss; }
    __syncthreads();
    if (t == 0) {
        float S = 0.f, SS = 0.f;
        #pragma unroll
        for (int i = 0; i < 8; i++) { S += rs[i]; SS += rss[i]; }
        const float invN = 1.f / (BATCH * NN);
        float mean = S * invN;
        float var  = SS * invN - mean * mean;
        float istd = rsqrtf(var + 1e-5f);
        float sc = gamma[c] * istd;
        d_scale[c] = sc;
        d_shift[c] = beta[c] - mean * sc;
    }
}

// ---------------------------------------------------------------------------
// out = BN(wy) + x
// ---------------------------------------------------------------------------
__global__ void k_final(const float* __restrict__ x, float* __restrict__ out)
{
    size_t i4 = (size_t)blockIdx.x * blockDim.x + threadIdx.x;
    if (i4 >= (size_t)BATCH * C_IN * NN / 4) return;
    int c = (int)((i4 >> 10) & (C_IN - 1));
    float sc = d_scale[c], sh = d_shift[c];
    float4 w  = ((const float4*)&d_wy[0][0][0])[i4];
    float4 xv = ((const float4*)x)[i4];
    float4 o;
    o.x = w.x * sc + sh + xv.x;
    o.y = w.y * sc + sh + xv.y;
    o.z = w.z * sc + sh + xv.z;
    o.w = w.w * sc + sh + xv.w;
    ((float4*)out)[i4] = o;
}

// ---------------------------------------------------------------------------
extern "C" void kernel_launch(void* const* d_in, const int* in_sizes, int n_in,
                              void* d_out, int out_size)
{
    const float* x       = (const float*)d_in[0];
    const float* w_g     = (const float*)d_in[1];
    const float* b_g     = (const float*)d_in[2];
    const float* w_theta = (const float*)d_in[3];
    const float* b_theta = (const float*)d_in[4];
    const float* w_phi   = (const float*)d_in[5];
    const float* b_phi   = (const float*)d_in[6];
    const float* w_w     = (const float*)d_in[7];
    const float* b_w     = (const float*)d_in[8];
    const float* gamma   = (const float*)d_in[9];
    const float* beta    = (const float*)d_in[10];
    float* out = (float*)d_out;

    cudaFuncSetAttribute(k_proj, cudaFuncAttributeMaxDynamicSharedMemorySize, DSM_GEMM);
    cudaFuncSetAttribute(k_attn, cudaFuncAttributeMaxDynamicSharedMemorySize, DSM_ATTN);
    cudaFuncSetAttribute(k_wy,   cudaFuncAttributeMaxDynamicSharedMemorySize, DSM_GEMM);

    k_xt   <<<dim3(NN / 32, C_IN / 32, BATCH), dim3(32, 8)>>>(x);
    k_wconv<<<512, 256>>>(w_theta, w_phi, w_g, w_w);
    k_proj <<<dim3(32, 3, BATCH), 256, DSM_GEMM>>>(b_theta, b_phi, b_g);
    k_attn <<<dim3(32, 1, BATCH), 512, DSM_ATTN>>>();
    k_wy   <<<dim3(32, 2, BATCH), 256, DSM_GEMM>>>(b_w);
    k_bnfin<<<C_IN, 256>>>(gamma, beta);
    k_final<<<(BATCH * C_IN * NN / 4 + 255) / 256, 256>>>(x, out);
}

// round 13
// speedup vs baseline: 1.4307x; 1.0909x over previous
#include <cuda_runtime.h>
#include <cuda_bf16.h>
#include <cuda_fp16.h>
#include <math.h>
#include <stdint.h>

#define BATCH 8
#define C_IN 256
#define C_I  128
#define NN   4096
#define MM   1024

// ---------------------------------------------------------------------------
// Scratch: operand planes + fp32 outputs
// x / weights / y: bf16 hi+lo (3-term GEMMs).  theta: fp16 hi+lo.  phi,g,P: fp16 single.
// ---------------------------------------------------------------------------
__device__ __align__(16) __nv_bfloat16 d_xTh[BATCH][NN][C_IN];
__device__ __align__(16) __nv_bfloat16 d_xTl[BATCH][NN][C_IN];
__device__ __align__(16) __half        d_thh[BATCH][NN][C_I];
__device__ __align__(16) __half        d_thl[BATCH][NN][C_I];
__device__ __align__(16) __half        d_phh[BATCH][MM][C_I];   // phi single fp16
__device__ __align__(16) __half        d_gh [BATCH][C_I][MM];   // g single fp16
__device__ __align__(16) __nv_bfloat16 d_yh [BATCH][NN][C_I];
__device__ __align__(16) __nv_bfloat16 d_yl [BATCH][NN][C_I];
__device__ __align__(16) __nv_bfloat16 d_wthh[C_I][C_IN], d_wthl[C_I][C_IN];
__device__ __align__(16) __nv_bfloat16 d_wphh[C_I][C_IN], d_wphl[C_I][C_IN];
__device__ __align__(16) __nv_bfloat16 d_wgh [C_I][C_IN], d_wgl [C_I][C_IN];
__device__ __align__(16) __nv_bfloat16 d_wwh [C_IN][C_I], d_wwl [C_IN][C_I];

__device__ float d_wy [BATCH][C_IN][NN];
__device__ float d_bns [BATCH][C_IN][128];
__device__ float d_bnss[BATCH][C_IN][128];
__device__ float d_scale[C_IN];
__device__ float d_shift[C_IN];

// ---------------------------------------------------------------------------
// helpers
// ---------------------------------------------------------------------------
__device__ __forceinline__ uint32_t smem_u32(const void* p) {
    uint32_t a;
    asm("{ .reg .u64 t; cvta.to.shared.u64 t, %1; cvt.u32.u64 %0, t; }" : "=r"(a) : "l"(p));
    return a;
}

#define LDSM_X4(r0, r1, r2, r3, addr) \
    asm volatile("ldmatrix.sync.aligned.m8n8.x4.shared.b16 {%0,%1,%2,%3}, [%4];" \
        : "=r"(r0), "=r"(r1), "=r"(r2), "=r"(r3) : "r"(addr))

#define MMA_BF16(c, a, b) \
    asm volatile("mma.sync.aligned.m16n8k16.row.col.f32.bf16.bf16.f32 " \
        "{%0,%1,%2,%3}, {%4,%5,%6,%7}, {%8,%9}, {%0,%1,%2,%3};" \
        : "+f"((c)[0]), "+f"((c)[1]), "+f"((c)[2]), "+f"((c)[3]) \
        : "r"((a)[0]), "r"((a)[1]), "r"((a)[2]), "r"((a)[3]), "r"((b)[0]), "r"((b)[1]))

#define MMA_FP16(c, a, b) \
    asm volatile("mma.sync.aligned.m16n8k16.row.col.f32.f16.f16.f32 " \
        "{%0,%1,%2,%3}, {%4,%5,%6,%7}, {%8,%9}, {%0,%1,%2,%3};" \
        : "+f"((c)[0]), "+f"((c)[1]), "+f"((c)[2]), "+f"((c)[3]) \
        : "r"((a)[0]), "r"((a)[1]), "r"((a)[2]), "r"((a)[3]), "r"((b)[0]), "r"((b)[1]))

#define CP_COMMIT()  asm volatile("cp.async.commit_group;" ::: "memory")
#define CP_WAIT(n)   asm volatile("cp.async.wait_group %0;" :: "n"(n) : "memory")

// bf16 hi/lo pair pack
__device__ __forceinline__ uint32_t pack2(float a, float b, uint32_t& lo)
{
    __nv_bfloat16 ha = __float2bfloat16(a), hb = __float2bfloat16(b);
    __nv_bfloat16 la = __float2bfloat16(a - __bfloat162float(ha));
    __nv_bfloat16 lb = __float2bfloat16(b - __bfloat162float(hb));
    lo = ((uint32_t)__bfloat16_as_ushort(lb) << 16) | __bfloat16_as_ushort(la);
    return ((uint32_t)__bfloat16_as_ushort(hb) << 16) | __bfloat16_as_ushort(ha);
}

// fp16 hi/lo pair pack
__device__ __forceinline__ uint32_t pack2h(float a, float b, uint32_t& lo)
{
    __half ha = __float2half_rn(a), hb = __float2half_rn(b);
    __half la = __float2half_rn(a - __half2float(ha));
    __half lb = __float2half_rn(b - __half2float(hb));
    lo = ((uint32_t)__half_as_ushort(lb) << 16) | __half_as_ushort(la);
    return ((uint32_t)__half_as_ushort(hb) << 16) | __half_as_ushort(ha);
}

// fp16 single pair pack
__device__ __forceinline__ uint32_t packh2(float a, float b)
{
    __half ha = __float2half_rn(a), hb = __float2half_rn(b);
    return ((uint32_t)__half_as_ushort(hb) << 16) | __half_as_ushort(ha);
}

__device__ __forceinline__ void split1(float v, __nv_bfloat16& h, __nv_bfloat16& l)
{
    h = __float2bfloat16(v);
    l = __float2bfloat16(v - __bfloat162float(h));
}

#define T_STRIDE 80
#define T_BYTES  (128 * T_STRIDE)            // 10240 (128-row tile)
#define DSM_GEMM (3 * 4 * T_BYTES + 128)
#define STG_LD   132

// async copy one 128x32 16-bit tile with 256 threads (2 x 16B per thread)
__device__ __forceinline__ void casync_tile(uint32_t dst, const uint16_t* __restrict__ src,
                                            int ld, int tid)
{
    #pragma unroll
    for (int i = 0; i < 2; i++) {
        int c = tid * 2 + i;
        int r = c >> 2, q = c & 3;
        const uint16_t* gp = src + (size_t)r * ld + q * 8;
        uint32_t sp = dst + (uint32_t)(r * T_STRIDE + q * 16);
        asm volatile("cp.async.cg.shared.global [%0], [%1], 16;" :: "r"(sp), "l"(gp) : "memory");
    }
}

// async copy one 128x32 16-bit tile with 512 threads (1 x 16B per thread)
__device__ __forceinline__ void casync_tile512(uint32_t dst, const uint16_t* __restrict__ src,
                                               int ld, int tid)
{
    int r = tid >> 2, q = tid & 3;
    const uint16_t* gp = src + (size_t)r * ld + q * 8;
    uint32_t sp = dst + (uint32_t)(r * T_STRIDE + q * 16);
    asm volatile("cp.async.cg.shared.global [%0], [%1], 16;" :: "r"(sp), "l"(gp) : "memory");
}

// one 32-K chunk, 4 m-frags, bf16 3-term (proj / wy, 256 threads)
__device__ __forceinline__ void mma_chunk(uint32_t tAh, uint32_t tAl, uint32_t tBh, uint32_t tBl,
                                          float acc[4][4][4],
                                          int arow, int brow, uint32_t acol0, uint32_t bcol0)
{
    #pragma unroll
    for (int kk = 0; kk < 2; kk++) {
        uint32_t ah[4][4], al[4][4], bh[4][2], bl[4][2];
        const uint32_t ka = (uint32_t)(kk * 32) + acol0;
        const uint32_t kb = (uint32_t)(kk * 32) + bcol0;
        #pragma unroll
        for (int mf = 0; mf < 4; mf++) {
            uint32_t ad = (uint32_t)(arow + mf * 16) * T_STRIDE + ka;
            LDSM_X4(ah[mf][0], ah[mf][1], ah[mf][2], ah[mf][3], tAh + ad);
            LDSM_X4(al[mf][0], al[mf][1], al[mf][2], al[mf][3], tAl + ad);
        }
        #pragma unroll
        for (int nf2 = 0; nf2 < 2; nf2++) {
            uint32_t bd = (uint32_t)(brow + nf2 * 16) * T_STRIDE + kb;
            uint32_t r0, r1, r2, r3;
            LDSM_X4(r0, r1, r2, r3, tBh + bd);
            bh[nf2 * 2][0] = r0; bh[nf2 * 2][1] = r1;
            bh[nf2 * 2 + 1][0] = r2; bh[nf2 * 2 + 1][1] = r3;
            LDSM_X4(r0, r1, r2, r3, tBl + bd);
            bl[nf2 * 2][0] = r0; bl[nf2 * 2][1] = r1;
            bl[nf2 * 2 + 1][0] = r2; bl[nf2 * 2 + 1][1] = r3;
        }
        #pragma unroll
        for (int mf = 0; mf < 4; mf++)
            #pragma unroll
            for (int nf = 0; nf < 4; nf++) {
                MMA_BF16(acc[mf][nf], ah[mf], bh[nf]);
                MMA_BF16(acc[mf][nf], ah[mf], bl[nf]);
                MMA_BF16(acc[mf][nf], al[mf], bh[nf]);
            }
    }
}

// one 32-K chunk, 2 m-frags, fp16 2-term: A hi/lo resident, B single (attn A)
__device__ __forceinline__ void mma_chunk2h(uint32_t tAh, uint32_t tAl, uint32_t tB,
                                            float acc[2][4][4],
                                            int arow, int brow, uint32_t acol0, uint32_t bcol0)
{
    #pragma unroll
    for (int kk = 0; kk < 2; kk++) {
        uint32_t ah[2][4], al[2][4], bf[4][2];
        const uint32_t ka = (uint32_t)(kk * 32) + acol0;
        const uint32_t kb = (uint32_t)(kk * 32) + bcol0;
        #pragma unroll
        for (int mf = 0; mf < 2; mf++) {
            uint32_t ad = (uint32_t)(arow + mf * 16) * T_STRIDE + ka;
            LDSM_X4(ah[mf][0], ah[mf][1], ah[mf][2], ah[mf][3], tAh + ad);
            LDSM_X4(al[mf][0], al[mf][1], al[mf][2], al[mf][3], tAl + ad);
        }
        #pragma unroll
        for (int nf2 = 0; nf2 < 2; nf2++) {
            uint32_t bd = (uint32_t)(brow + nf2 * 16) * T_STRIDE + kb;
            uint32_t r0, r1, r2, r3;
            LDSM_X4(r0, r1, r2, r3, tB + bd);
            bf[nf2 * 2][0] = r0; bf[nf2 * 2][1] = r1;
            bf[nf2 * 2 + 1][0] = r2; bf[nf2 * 2 + 1][1] = r3;
        }
        #pragma unroll
        for (int mf = 0; mf < 2; mf++)
            #pragma unroll
            for (int nf = 0; nf < 4; nf++) {
                MMA_FP16(acc[mf][nf], ah[mf], bf[nf]);
                MMA_FP16(acc[mf][nf], al[mf], bf[nf]);
            }
    }
}

// one 32-K chunk, 2 m-frags, fp16 1-term: A single resident, B single (attn C)
__device__ __forceinline__ void mma_chunk1h(uint32_t tA, uint32_t tB,
                                            float acc[2][4][4],
                                            int arow, int brow, uint32_t acol0, uint32_t bcol0)
{
    #pragma unroll
    for (int kk = 0; kk < 2; kk++) {
        uint32_t af[2][4], bf[4][2];
        const uint32_t ka = (uint32_t)(kk * 32) + acol0;
        const uint32_t kb = (uint32_t)(kk * 32) + bcol0;
        #pragma unroll
        for (int mf = 0; mf < 2; mf++) {
            uint32_t ad = (uint32_t)(arow + mf * 16) * T_STRIDE + ka;
            LDSM_X4(af[mf][0], af[mf][1], af[mf][2], af[mf][3], tA + ad);
        }
        #pragma unroll
        for (int nf2 = 0; nf2 < 2; nf2++) {
            uint32_t bd = (uint32_t)(brow + nf2 * 16) * T_STRIDE + kb;
            uint32_t r0, r1, r2, r3;
            LDSM_X4(r0, r1, r2, r3, tB + bd);
            bf[nf2 * 2][0] = r0; bf[nf2 * 2][1] = r1;
            bf[nf2 * 2 + 1][0] = r2; bf[nf2 * 2 + 1][1] = r3;
        }
        #pragma unroll
        for (int mf = 0; mf < 2; mf++)
            #pragma unroll
            for (int nf = 0; nf < 4; nf++)
                MMA_FP16(acc[mf][nf], af[mf], bf[nf]);
    }
}

// ---------------------------------------------------------------------------
// Streamed GEMM (128x128 out, 256 threads, bf16 3-term): 3-stage cp.async ring.
// ---------------------------------------------------------------------------
__device__ __forceinline__ void gemm_stream(
    const __nv_bfloat16* __restrict__ Ah, const __nv_bfloat16* __restrict__ Al, int ldA,
    const __nv_bfloat16* __restrict__ Bh, const __nv_bfloat16* __restrict__ Bl, int ldB,
    int nk, float acc[4][4][4], uint32_t base, int tid,
    int arow, int brow, uint32_t acol0, uint32_t bcol0)
{
    __syncthreads();
    #pragma unroll
    for (int s = 0; s < 2; s++) {
        uint32_t st = base + (uint32_t)(s * 4 * T_BYTES);
        casync_tile(st,               (const uint16_t*)(Ah + s * 32), ldA, tid);
        casync_tile(st + T_BYTES,     (const uint16_t*)(Al + s * 32), ldA, tid);
        casync_tile(st + 2 * T_BYTES, (const uint16_t*)(Bh + s * 32), ldB, tid);
        casync_tile(st + 3 * T_BYTES, (const uint16_t*)(Bl + s * 32), ldB, tid);
        CP_COMMIT();
    }
    for (int ks = 0; ks < nk; ks++) {
        if (ks < nk - 1) CP_WAIT(1); else CP_WAIT(0);
        __syncthreads();
        if (ks + 2 < nk) {
            uint32_t st = base + (uint32_t)(((ks + 2) % 3) * 4 * T_BYTES);
            casync_tile(st,               (const uint16_t*)(Ah + (ks + 2) * 32), ldA, tid);
            casync_tile(st + T_BYTES,     (const uint16_t*)(Al + (ks + 2) * 32), ldA, tid);
            casync_tile(st + 2 * T_BYTES, (const uint16_t*)(Bh + (ks + 2) * 32), ldB, tid);
            casync_tile(st + 3 * T_BYTES, (const uint16_t*)(Bl + (ks + 2) * 32), ldB, tid);
            CP_COMMIT();
        }
        uint32_t st = base + (uint32_t)((ks % 3) * 4 * T_BYTES);
        mma_chunk(st, st + T_BYTES, st + 2 * T_BYTES, st + 3 * T_BYTES,
                  acc, arow, brow, acol0, bcol0);
    }
}

// ---------------------------------------------------------------------------
// A-resident fp16 2-term GEMM (attn phase A, 512 threads): B single streamed.
// ---------------------------------------------------------------------------
__device__ __forceinline__ void gemm_ares2(
    uint32_t aTiles, const uint16_t* __restrict__ B, int ldB,
    uint32_t stg, float acc[2][4][4], int tid,
    int arow, int brow, uint32_t acol0, uint32_t bcol0)
{
    __syncthreads();
    #pragma unroll
    for (int s = 0; s < 2; s++) {
        casync_tile512(stg + (uint32_t)(s * T_BYTES), B + s * 32, ldB, tid);
        CP_COMMIT();
    }
    #pragma unroll
    for (int kc = 0; kc < 4; kc++) {
        if (kc < 3) CP_WAIT(1); else CP_WAIT(0);
        __syncthreads();
        if (kc + 2 < 4) {
            casync_tile512(stg + (uint32_t)(((kc + 2) % 3) * T_BYTES), B + (kc + 2) * 32, ldB, tid);
            CP_COMMIT();
        }
        mma_chunk2h(aTiles + (uint32_t)(kc * 2) * T_BYTES,
                    aTiles + (uint32_t)(kc * 2 + 1) * T_BYTES,
                    stg + (uint32_t)((kc % 3) * T_BYTES),
                    acc, arow, brow, acol0, bcol0);
    }
}

// ---------------------------------------------------------------------------
// A-resident fp16 1-term GEMM (attn phase C, 512 threads): B single streamed.
// ---------------------------------------------------------------------------
__device__ __forceinline__ void gemm_ares1(
    uint32_t aTiles, const uint16_t* __restrict__ B, int ldB,
    uint32_t stg, float acc[2][4][4], int tid,
    int arow, int brow, uint32_t acol0, uint32_t bcol0)
{
    __syncthreads();
    #pragma unroll
    for (int s = 0; s < 2; s++) {
        casync_tile512(stg + (uint32_t)(s * T_BYTES), B + s * 32, ldB, tid);
        CP_COMMIT();
    }
    #pragma unroll
    for (int kc = 0; kc < 4; kc++) {
        if (kc < 3) CP_WAIT(1); else CP_WAIT(0);
        __syncthreads();
        if (kc + 2 < 4) {
            casync_tile512(stg + (uint32_t)(((kc + 2) % 3) * T_BYTES), B + (kc + 2) * 32, ldB, tid);
            CP_COMMIT();
        }
        mma_chunk1h(aTiles + (uint32_t)(kc * T_BYTES),
                    stg + (uint32_t)((kc % 3) * T_BYTES),
                    acc, arow, brow, acol0, bcol0);
    }
}

// 128-row fragment geometry (proj / wy; 8 warps 2x4)
#define FRAG_SETUP() \
    const int lane = threadIdx.x & 31, wid = threadIdx.x >> 5; \
    const int warp_m = wid >> 2, warp_n = wid & 3; \
    const int g = lane >> 2, t2 = (lane & 3) * 2; \
    (void)warp_m; (void)warp_n; (void)g; (void)t2
#define FROW(mf, h) (warp_m * 64 + (mf) * 16 + g + (h) * 8)
#define FCOL(nf)    (warp_n * 32 + (nf) * 8 + t2)
#define GEOM_SETUP() \
    const int arow = warp_m * 64 + (lane & 15); \
    const int brow = warp_n * 32 + (lane & 7) + ((lane >> 4) << 3); \
    const uint32_t acol0 = (uint32_t)((lane >> 4) << 4); \
    const uint32_t bcol0 = (uint32_t)(((lane >> 3) & 1) << 4)

// attn geometry (16 warps 4x4, 32x32 per warp)
#define FROW32(mf, h) (warp_m * 32 + (mf) * 16 + g + (h) * 8)

// ---------------------------------------------------------------------------
// Transpose + split x (bf16 hi/lo)
// ---------------------------------------------------------------------------
__global__ void k_xt(const float* __restrict__ x)
{
    __shared__ float t[32][33];
    const int b = blockIdx.z, c0 = blockIdx.y * 32, n0 = blockIdx.x * 32;
    const int tx = threadIdx.x, ty = threadIdx.y;
    const float* src = x + ((size_t)b * C_IN + c0) * NN + n0;
    #pragma unroll
    for (int i = 0; i < 32; i += 8) t[ty + i][tx] = src[(size_t)(ty + i) * NN + tx];
    __syncthreads();
    #pragma unroll
    for (int i = 0; i < 32; i += 8) {
        __nv_bfloat16 h, l;
        split1(t[tx][ty + i], h, l);
        d_xTh[b][n0 + ty + i][c0 + tx] = h;
        d_xTl[b][n0 + ty + i][c0 + tx] = l;
    }
}

// ---------------------------------------------------------------------------
// Convert weights to bf16 hi/lo planes
// ---------------------------------------------------------------------------
__global__ void k_wconv(const float* __restrict__ wth, const float* __restrict__ wph,
                        const float* __restrict__ wg,  const float* __restrict__ ww)
{
    int i = blockIdx.x * 256 + threadIdx.x;
    const float* src; __nv_bfloat16 *dh, *dl; int off;
    if (i < 32768)       { src = wth; dh = &d_wthh[0][0]; dl = &d_wthl[0][0]; off = i; }
    else if (i < 65536)  { src = wph; dh = &d_wphh[0][0]; dl = &d_wphl[0][0]; off = i - 32768; }
    else if (i < 98304)  { src = wg;  dh = &d_wgh[0][0];  dl = &d_wgl[0][0];  off = i - 65536; }
    else                 { src = ww;  dh = &d_wwh[0][0];  dl = &d_wwl[0][0];  off = i - 98304; }
    __nv_bfloat16 h, l;
    split1(src[off], h, l);
    dh[off] = h; dl[off] = l;
}

// ---------------------------------------------------------------------------
// Projections (bf16 3-term): theta -> fp16 hi/lo; phi, g -> single fp16
// ---------------------------------------------------------------------------
__global__ __launch_bounds__(256) void k_proj(
    const float* __restrict__ b_theta, const float* __restrict__ b_phi,
    const float* __restrict__ b_g)
{
    extern __shared__ char dsm[];
    const uint32_t base = (smem_u32(dsm) + 127u) & ~127u;
    const int b  = blockIdx.z;
    const int nT = blockIdx.x * 128;
    const __nv_bfloat16 *Wh, *Wl; const float* Bp;
    if (blockIdx.y == 0)      { Wh = &d_wthh[0][0]; Wl = &d_wthl[0][0]; Bp = b_theta; }
    else if (blockIdx.y == 1) { Wh = &d_wphh[0][0]; Wl = &d_wphl[0][0]; Bp = b_phi;   }
    else                      { Wh = &d_wgh[0][0];  Wl = &d_wgl[0][0];  Bp = b_g;     }

    FRAG_SETUP();
    GEOM_SETUP();
    const int tid = threadIdx.x;
    float acc[4][4][4] = {};
    gemm_stream(&d_xTh[b][nT][0], &d_xTl[b][nT][0], C_IN, Wh, Wl, C_IN,
                C_IN / 32, acc, base, tid, arow, brow, acol0, bcol0);

    if (blockIdx.y == 0) {
        #pragma unroll
        for (int mf = 0; mf < 4; mf++)
            #pragma unroll
            for (int nf = 0; nf < 4; nf++) {
                int col = FCOL(nf);
                float2 bias = *(const float2*)&Bp[col];
                int r0 = FROW(mf, 0), r1 = FROW(mf, 1);
                uint32_t lo, hi;
                hi = pack2h(acc[mf][nf][0] + bias.x, acc[mf][nf][1] + bias.y, lo);
                *(uint32_t*)&d_thh[b][nT + r0][col] = hi;
                *(uint32_t*)&d_thl[b][nT + r0][col] = lo;
                hi = pack2h(acc[mf][nf][2] + bias.x, acc[mf][nf][3] + bias.y, lo);
                *(uint32_t*)&d_thh[b][nT + r1][col] = hi;
                *(uint32_t*)&d_thl[b][nT + r1][col] = lo;
            }
    } else {
        float* stg = (float*)dsm;
        __syncthreads();
        #pragma unroll
        for (int mf = 0; mf < 4; mf++)
            #pragma unroll
            for (int nf = 0; nf < 4; nf++) {
                int col = FCOL(nf);
                int r0 = FROW(mf, 0), r1 = FROW(mf, 1);
                stg[col * STG_LD + r0]       = acc[mf][nf][0];
                stg[(col + 1) * STG_LD + r0] = acc[mf][nf][1];
                stg[col * STG_LD + r1]       = acc[mf][nf][2];
                stg[(col + 1) * STG_LD + r1] = acc[mf][nf][3];
            }
        __syncthreads();
        const int m0 = blockIdx.x * 32;
        const int t = threadIdx.x;
        if (blockIdx.y == 1) {
            #pragma unroll
            for (int ob = 0; ob < 4; ob++) {
                int oo = ob * 32 + (t & 31);
                #pragma unroll
                for (int i = 0; i < 4; i++) {
                    int wp = (t >> 5) + i * 8;
                    float2 a = *(const float2*)&stg[oo * STG_LD + 2 * wp];
                    float2 c = *(const float2*)&stg[oo * STG_LD + 64 + 2 * wp];
                    float v = fmaxf(fmaxf(a.x, a.y), fmaxf(c.x, c.y)) + Bp[oo];
                    d_phh[b][m0 + wp][oo] = __float2half_rn(v);
                }
            }
        } else {
            const int wp = t & 31;
            #pragma unroll
            for (int i = 0; i < 16; i++) {
                int o = (t >> 5) + i * 8;
                float2 a = *(const float2*)&stg[o * STG_LD + 2 * wp];
                float2 c = *(const float2*)&stg[o * STG_LD + 64 + 2 * wp];
                float v = fmaxf(fmaxf(a.x, a.y), fmaxf(c.x, c.y)) + Bp[o];
                d_gh[b][o][m0 + wp] = __float2half_rn(v);
            }
        }
    }
}

// ---------------------------------------------------------------------------
// Fused attention, 128-row n-tile, 512 threads.
// phase A: theta(hi/lo) x phi(single) — 2 MMAs/k16 (as in R10)
// phase C: P(single)    x g(single)   — 1 MMA /k16 (the single new cut)
// smem: [thA 81920][P 40960][Bstg 30720][red 2048]
// ---------------------------------------------------------------------------
#define ATTN_THA   0
#define ATTN_P     (8 * T_BYTES)
#define ATTN_BSTG  (ATTN_P + 4 * T_BYTES)
#define ATTN_RED   (ATTN_BSTG + 3 * T_BYTES)
#define DSM_ATTN   (ATTN_RED + 2048 + 128)

__global__ __launch_bounds__(512) void k_attn()
{
    extern __shared__ char dsm[];
    char* dsma = (char*)((((uintptr_t)dsm) + 127) & ~(uintptr_t)127);
    const uint32_t base = smem_u32(dsma);
    const uint32_t thA  = base + ATTN_THA;
    const uint32_t Pb   = base + ATTN_P;
    const uint32_t Bstg = base + ATTN_BSTG;
    float* redbuf = (float*)(dsma + ATTN_RED);

    const int b  = blockIdx.z;
    const int nT = blockIdx.x * 128;
    const int tid = threadIdx.x;
    const int lane = tid & 31, wid = tid >> 5;
    const int warp_m = wid >> 2, warp_n = wid & 3;
    const int g = lane >> 2, t2 = (lane & 3) * 2;
    const int arow = warp_m * 32 + (lane & 15);
    const int brow = warp_n * 32 + (lane & 7) + ((lane >> 4) << 3);
    const uint32_t acol0 = (uint32_t)((lane >> 4) << 4);
    const uint32_t bcol0 = (uint32_t)(((lane >> 3) & 1) << 4);

    // load theta tile (128 rows x 128 K, fp16 hi/lo) once
    {
        const uint16_t* Ah = (const uint16_t*)&d_thh[b][nT][0];
        const uint16_t* Al = (const uint16_t*)&d_thl[b][nT][0];
        #pragma unroll
        for (int kc = 0; kc < 4; kc++) {
            casync_tile512(thA + (uint32_t)(kc * 2) * T_BYTES,     Ah + kc * 32, C_I, tid);
            casync_tile512(thA + (uint32_t)(kc * 2 + 1) * T_BYTES, Al + kc * 32, C_I, tid);
        }
        CP_COMMIT();
        CP_WAIT(0);
        __syncthreads();
    }

    float yacc[2][4][4] = {};
    float ps[2][2] = {};

    for (int mt = 0; mt < 8; mt++) {
        const int mT = mt * 128;

        // phase A: scores
        float facc[2][4][4] = {};
        gemm_ares2(thA, (const uint16_t*)&d_phh[b][mT][0], C_I,
                   Bstg, facc, tid, arow, brow, acol0, bcol0);

        // phase B: exp + row partials + P -> smem single fp16 (warp_n owns chunk)
        const uint32_t Ph = Pb + (uint32_t)warp_n * T_BYTES;
        #pragma unroll
        for (int mf = 0; mf < 2; mf++) {
            const int r0 = FROW32(mf, 0), r1 = FROW32(mf, 1);
            #pragma unroll
            for (int nf = 0; nf < 4; nf++) {
                float e0 = __expf(facc[mf][nf][0]);
                float e1 = __expf(facc[mf][nf][1]);
                float e2 = __expf(facc[mf][nf][2]);
                float e3 = __expf(facc[mf][nf][3]);
                ps[mf][0] += e0 + e1;
                ps[mf][1] += e2 + e3;
                uint32_t hi0 = packh2(e0, e1);
                uint32_t hi1 = packh2(e2, e3);
                uint32_t off0 = (uint32_t)(r0 * T_STRIDE + (nf * 8 + t2) * 2);
                uint32_t off1 = (uint32_t)(r1 * T_STRIDE + (nf * 8 + t2) * 2);
                asm volatile("st.shared.b32 [%0], %1;" :: "r"(Ph + off0), "r"(hi0));
                asm volatile("st.shared.b32 [%0], %1;" :: "r"(Ph + off1), "r"(hi1));
            }
        }

        // phase C: yacc += P · g^T (1 MMA per k16)
        gemm_ares1(Pb, (const uint16_t*)&d_gh[b][0][mT], MM,
                   Bstg, yacc, tid, arow, brow, acol0, bcol0);
    }

    // epilogue: cross-warp row sums, normalize, write y planes (bf16 hi/lo)
    #pragma unroll
    for (int mf = 0; mf < 2; mf++)
        #pragma unroll
        for (int h = 0; h < 2; h++) {
            float v = ps[mf][h];
            v += __shfl_xor_sync(0xffffffffu, v, 1);
            v += __shfl_xor_sync(0xffffffffu, v, 2);
            if ((lane & 3) == 0) redbuf[warp_n * 128 + FROW32(mf, h)] = v;
        }
    __syncthreads();
    #pragma unroll
    for (int mf = 0; mf < 2; mf++)
        #pragma unroll
        for (int h = 0; h < 2; h++) {
            int row = FROW32(mf, h);
            float iv = 1.f / (redbuf[row] + redbuf[128 + row] +
                              redbuf[256 + row] + redbuf[384 + row]);
            #pragma unroll
            for (int nf = 0; nf < 4; nf++) {
                float c0 = yacc[mf][nf][2 * h]     * iv;
                float c1 = yacc[mf][nf][2 * h + 1] * iv;
                uint32_t lo, hi = pack2(c0, c1, lo);
                *(uint32_t*)&d_yh[b][nT + row][warp_n * 32 + nf * 8 + t2] = hi;
                *(uint32_t*)&d_yl[b][nT + row][warp_n * 32 + nf * 8 + t2] = lo;
            }
        }
}

// ---------------------------------------------------------------------------
// wy (bf16 3-term, exactly as R10)
// ---------------------------------------------------------------------------
__global__ __launch_bounds__(256) void k_wy(const float* __restrict__ b_w)
{
    extern __shared__ char dsm[];
    const uint32_t base = (smem_u32(dsm) + 127u) & ~127u;
    const int b  = blockIdx.z;
    const int cT = blockIdx.y * 128;
    const int nT = blockIdx.x * 128;

    FRAG_SETUP();
    GEOM_SETUP();
    const int tid = threadIdx.x;
    float acc[4][4][4] = {};
    gemm_stream(&d_wwh[cT][0], &d_wwl[cT][0], C_I,
                &d_yh[b][nT][0], &d_yl[b][nT][0], C_I,
                C_I / 32, acc, base, tid, arow, brow, acol0, bcol0);

    const int sub = blockIdx.x * 4 + warp_n;
    #pragma unroll
    for (int mf = 0; mf < 4; mf++)
        #pragma unroll
        for (int h = 0; h < 2; h++) {
            int row = FROW(mf, h);
            int c = cT + row;
            float bias = b_w[c];
            float s = 0.f, ss = 0.f;
            #pragma unroll
            for (int nf = 0; nf < 4; nf++) {
                float c0 = acc[mf][nf][2 * h]     + bias;
                float c1 = acc[mf][nf][2 * h + 1] + bias;
                s += c0 + c1;
                ss += c0 * c0 + c1 * c1;
                *(float2*)&d_wy[b][c][nT + FCOL(nf)] = make_float2(c0, c1);
            }
            s  += __shfl_xor_sync(0xffffffffu, s, 1);
            s  += __shfl_xor_sync(0xffffffffu, s, 2);
            ss += __shfl_xor_sync(0xffffffffu, ss, 1);
            ss += __shfl_xor_sync(0xffffffffu, ss, 2);
            if ((lane & 3) == 0) { d_bns[b][c][sub] = s; d_bnss[b][c][sub] = ss; }
        }
}

// ---------------------------------------------------------------------------
// BN finalize
// ---------------------------------------------------------------------------
__global__ void k_bnfin(const float* __restrict__ gamma, const float* __restrict__ beta)
{
    const int c = blockIdx.x;
    const int t = threadIdx.x;
    float s = 0.f, ss = 0.f;
    #pragma unroll
    for (int i = 0; i < 4; i++) {
        int id = t + i * 256;
        int b = id >> 7, tile = id & 127;
        s  += d_bns [b][c][tile];
        ss += d_bnss[b][c][tile];
    }
    const int lane = t & 31, warp = t >> 5;
    #pragma unroll
    for (int o = 16; o > 0; o >>= 1) {
        s  += __shfl_xor_sync(0xffffffffu, s, o);
        ss += __shfl_xor_sync(0xffffffffu, ss, o);
    }
    __shared__ float rs[8], rss[8];
    if (lane == 0) { rs[warp] = s; rss[warp] = ss; }
    __syncthreads();
    if (t == 0) {
        float S = 0.f, SS = 0.f;
        #pragma unroll
        for (int i = 0; i < 8; i++) { S += rs[i]; SS += rss[i]; }
        const float invN = 1.f / (BATCH * NN);
        float mean = S * invN;
        float var  = SS * invN - mean * mean;
        float istd = rsqrtf(var + 1e-5f);
        float sc = gamma[c] * istd;
        d_scale[c] = sc;
        d_shift[c] = beta[c] - mean * sc;
    }
}

// ---------------------------------------------------------------------------
// out = BN(wy) + x
// ---------------------------------------------------------------------------
__global__ void k_final(const float* __restrict__ x, float* __restrict__ out)
{
    size_t i4 = (size_t)blockIdx.x * blockDim.x + threadIdx.x;
    if (i4 >= (size_t)BATCH * C_IN * NN / 4) return;
    int c = (int)((i4 >> 10) & (C_IN - 1));
    float sc = d_scale[c], sh = d_shift[c];
    float4 w  = ((const float4*)&d_wy[0][0][0])[i4];
    float4 xv = ((const float4*)x)[i4];
    float4 o;
    o.x = w.x * sc + sh + xv.x;
    o.y = w.y * sc + sh + xv.y;
    o.z = w.z * sc + sh + xv.z;
    o.w = w.w * sc + sh + xv.w;
    ((float4*)out)[i4] = o;
}

// ---------------------------------------------------------------------------
extern "C" void kernel_launch(void* const* d_in, const int* in_sizes, int n_in,
                              void* d_out, int out_size)
{
    const float* x       = (const float*)d_in[0];
    const float* w_g     = (const float*)d_in[1];
    const float* b_g     = (const float*)d_in[2];
    const float* w_theta = (const float*)d_in[3];
    const float* b_theta = (const float*)d_in[4];
    const float* w_phi   = (const float*)d_in[5];
    const float* b_phi   = (const float*)d_in[6];
    const float* w_w     = (const float*)d_in[7];
    const float* b_w     = (const float*)d_in[8];
    const float* gamma   = (const float*)d_in[9];
    const float* beta    = (const float*)d_in[10];
    float* out = (float*)d_out;

    cudaFuncSetAttribute(k_proj, cudaFuncAttributeMaxDynamicSharedMemorySize, DSM_GEMM);
    cudaFuncSetAttribute(k_attn, cudaFuncAttributeMaxDynamicSharedMemorySize, DSM_ATTN);
    cudaFuncSetAttribute(k_wy,   cudaFuncAttributeMaxDynamicSharedMemorySize, DSM_GEMM);

    k_xt   <<<dim3(NN / 32, C_IN / 32, BATCH), dim3(32, 8)>>>(x);
    k_wconv<<<512, 256>>>(w_theta, w_phi, w_g, w_w);
    k_proj <<<dim3(32, 3, BATCH), 256, DSM_GEMM>>>(b_theta, b_phi, b_g);
    k_attn <<<dim3(32, 1, BATCH), 512, DSM_ATTN>>>();
    k_wy   <<<dim3(32, 2, BATCH), 256, DSM_GEMM>>>(b_w);
    k_bnfin<<<C_IN, 256>>>(gamma, beta);
    k_final<<<(BATCH * C_IN * NN / 4 + 255) / 256, 256>>>(x, out);
}

// round 15
// speedup vs baseline: 1.5232x; 1.0646x over previous
#include <cuda_runtime.h>
#include <cuda_bf16.h>
#include <cuda_fp16.h>
#include <math.h>
#include <stdint.h>

#define BATCH 8
#define C_IN 256
#define C_I  128
#define NN   4096
#define MM   1024

// ---------------------------------------------------------------------------
// Scratch
// x / W / w_w / y: bf16 hi+lo (3-term, BN-critical path).
// theta, phi, g, P: fp16 single (attention-internal, safe).
// ---------------------------------------------------------------------------
__device__ __align__(16) __nv_bfloat16 d_xTh[BATCH][NN][C_IN];
__device__ __align__(16) __nv_bfloat16 d_xTl[BATCH][NN][C_IN];
__device__ __align__(16) __half        d_th [BATCH][NN][C_I];   // theta single fp16
__device__ __align__(16) __half        d_phh[BATCH][MM][C_I];   // phi single fp16
__device__ __align__(16) __half        d_gh [BATCH][C_I][MM];   // g single fp16
__device__ __align__(16) __nv_bfloat16 d_yh [BATCH][NN][C_I];
__device__ __align__(16) __nv_bfloat16 d_yl [BATCH][NN][C_I];
__device__ __align__(16) __nv_bfloat16 d_wthh[C_I][C_IN], d_wthl[C_I][C_IN];
__device__ __align__(16) __nv_bfloat16 d_wphh[C_I][C_IN], d_wphl[C_I][C_IN];
__device__ __align__(16) __nv_bfloat16 d_wgh [C_I][C_IN], d_wgl [C_I][C_IN];
__device__ __align__(16) __nv_bfloat16 d_wwh [C_IN][C_I], d_wwl [C_IN][C_I];

__device__ float d_wy [BATCH][C_IN][NN];
__device__ float d_bns [BATCH][C_IN][128];
__device__ float d_bnss[BATCH][C_IN][128];
__device__ float d_scale[C_IN];
__device__ float d_shift[C_IN];

// ---------------------------------------------------------------------------
// helpers
// ---------------------------------------------------------------------------
__device__ __forceinline__ uint32_t smem_u32(const void* p) {
    uint32_t a;
    asm("{ .reg .u64 t; cvta.to.shared.u64 t, %1; cvt.u32.u64 %0, t; }" : "=r"(a) : "l"(p));
    return a;
}

#define LDSM_X4(r0, r1, r2, r3, addr) \
    asm volatile("ldmatrix.sync.aligned.m8n8.x4.shared.b16 {%0,%1,%2,%3}, [%4];" \
        : "=r"(r0), "=r"(r1), "=r"(r2), "=r"(r3) : "r"(addr))

#define MMA_BF16(c, a, b) \
    asm volatile("mma.sync.aligned.m16n8k16.row.col.f32.bf16.bf16.f32 " \
        "{%0,%1,%2,%3}, {%4,%5,%6,%7}, {%8,%9}, {%0,%1,%2,%3};" \
        : "+f"((c)[0]), "+f"((c)[1]), "+f"((c)[2]), "+f"((c)[3]) \
        : "r"((a)[0]), "r"((a)[1]), "r"((a)[2]), "r"((a)[3]), "r"((b)[0]), "r"((b)[1]))

#define MMA_FP16(c, a, b) \
    asm volatile("mma.sync.aligned.m16n8k16.row.col.f32.f16.f16.f32 " \
        "{%0,%1,%2,%3}, {%4,%5,%6,%7}, {%8,%9}, {%0,%1,%2,%3};" \
        : "+f"((c)[0]), "+f"((c)[1]), "+f"((c)[2]), "+f"((c)[3]) \
        : "r"((a)[0]), "r"((a)[1]), "r"((a)[2]), "r"((a)[3]), "r"((b)[0]), "r"((b)[1]))

#define CP_COMMIT()  asm volatile("cp.async.commit_group;" ::: "memory")
#define CP_WAIT(n)   asm volatile("cp.async.wait_group %0;" :: "n"(n) : "memory")

// bf16 hi/lo pair pack
__device__ __forceinline__ uint32_t pack2(float a, float b, uint32_t& lo)
{
    __nv_bfloat16 ha = __float2bfloat16(a), hb = __float2bfloat16(b);
    __nv_bfloat16 la = __float2bfloat16(a - __bfloat162float(ha));
    __nv_bfloat16 lb = __float2bfloat16(b - __bfloat162float(hb));
    lo = ((uint32_t)__bfloat16_as_ushort(lb) << 16) | __bfloat16_as_ushort(la);
    return ((uint32_t)__bfloat16_as_ushort(hb) << 16) | __bfloat16_as_ushort(ha);
}

// fp16 single pair pack
__device__ __forceinline__ uint32_t packh2(float a, float b)
{
    __half ha = __float2half_rn(a), hb = __float2half_rn(b);
    return ((uint32_t)__half_as_ushort(hb) << 16) | __half_as_ushort(ha);
}

__device__ __forceinline__ void split1(float v, __nv_bfloat16& h, __nv_bfloat16& l)
{
    h = __float2bfloat16(v);
    l = __float2bfloat16(v - __bfloat162float(h));
}

#define T_STRIDE 80
#define T_BYTES  (128 * T_STRIDE)            // 10240 (128-row tile)
#define DSM_GEMM (3 * 4 * T_BYTES + 128)
#define STG_LD   132

// async copy one 128x32 16-bit tile with 256 threads (2 x 16B per thread)
__device__ __forceinline__ void casync_tile(uint32_t dst, const uint16_t* __restrict__ src,
                                            int ld, int tid)
{
    #pragma unroll
    for (int i = 0; i < 2; i++) {
        int c = tid * 2 + i;
        int r = c >> 2, q = c & 3;
        const uint16_t* gp = src + (size_t)r * ld + q * 8;
        uint32_t sp = dst + (uint32_t)(r * T_STRIDE + q * 16);
        asm volatile("cp.async.cg.shared.global [%0], [%1], 16;" :: "r"(sp), "l"(gp) : "memory");
    }
}

// async copy one 128x32 16-bit tile with 512 threads (1 x 16B per thread)
__device__ __forceinline__ void casync_tile512(uint32_t dst, const uint16_t* __restrict__ src,
                                               int ld, int tid)
{
    int r = tid >> 2, q = tid & 3;
    const uint16_t* gp = src + (size_t)r * ld + q * 8;
    uint32_t sp = dst + (uint32_t)(r * T_STRIDE + q * 16);
    asm volatile("cp.async.cg.shared.global [%0], [%1], 16;" :: "r"(sp), "l"(gp) : "memory");
}

// one 32-K chunk, 4 m-frags, bf16 3-term (proj / wy, 256 threads)
__device__ __forceinline__ void mma_chunk(uint32_t tAh, uint32_t tAl, uint32_t tBh, uint32_t tBl,
                                          float acc[4][4][4],
                                          int arow, int brow, uint32_t acol0, uint32_t bcol0)
{
    #pragma unroll
    for (int kk = 0; kk < 2; kk++) {
        uint32_t ah[4][4], al[4][4], bh[4][2], bl[4][2];
        const uint32_t ka = (uint32_t)(kk * 32) + acol0;
        const uint32_t kb = (uint32_t)(kk * 32) + bcol0;
        #pragma unroll
        for (int mf = 0; mf < 4; mf++) {
            uint32_t ad = (uint32_t)(arow + mf * 16) * T_STRIDE + ka;
            LDSM_X4(ah[mf][0], ah[mf][1], ah[mf][2], ah[mf][3], tAh + ad);
            LDSM_X4(al[mf][0], al[mf][1], al[mf][2], al[mf][3], tAl + ad);
        }
        #pragma unroll
        for (int nf2 = 0; nf2 < 2; nf2++) {
            uint32_t bd = (uint32_t)(brow + nf2 * 16) * T_STRIDE + kb;
            uint32_t r0, r1, r2, r3;
            LDSM_X4(r0, r1, r2, r3, tBh + bd);
            bh[nf2 * 2][0] = r0; bh[nf2 * 2][1] = r1;
            bh[nf2 * 2 + 1][0] = r2; bh[nf2 * 2 + 1][1] = r3;
            LDSM_X4(r0, r1, r2, r3, tBl + bd);
            bl[nf2 * 2][0] = r0; bl[nf2 * 2][1] = r1;
            bl[nf2 * 2 + 1][0] = r2; bl[nf2 * 2 + 1][1] = r3;
        }
        #pragma unroll
        for (int mf = 0; mf < 4; mf++)
            #pragma unroll
            for (int nf = 0; nf < 4; nf++) {
                MMA_BF16(acc[mf][nf], ah[mf], bh[nf]);
                MMA_BF16(acc[mf][nf], ah[mf], bl[nf]);
                MMA_BF16(acc[mf][nf], al[mf], bh[nf]);
            }
    }
}

// one 32-K chunk, 2 m-frags, fp16 1-term: A single resident, B single (attn A & C)
__device__ __forceinline__ void mma_chunk1h(uint32_t tA, uint32_t tB,
                                            float acc[2][4][4],
                                            int arow, int brow, uint32_t acol0, uint32_t bcol0)
{
    #pragma unroll
    for (int kk = 0; kk < 2; kk++) {
        uint32_t af[2][4], bf[4][2];
        const uint32_t ka = (uint32_t)(kk * 32) + acol0;
        const uint32_t kb = (uint32_t)(kk * 32) + bcol0;
        #pragma unroll
        for (int mf = 0; mf < 2; mf++) {
            uint32_t ad = (uint32_t)(arow + mf * 16) * T_STRIDE + ka;
            LDSM_X4(af[mf][0], af[mf][1], af[mf][2], af[mf][3], tA + ad);
        }
        #pragma unroll
        for (int nf2 = 0; nf2 < 2; nf2++) {
            uint32_t bd = (uint32_t)(brow + nf2 * 16) * T_STRIDE + kb;
            uint32_t r0, r1, r2, r3;
            LDSM_X4(r0, r1, r2, r3, tB + bd);
            bf[nf2 * 2][0] = r0; bf[nf2 * 2][1] = r1;
            bf[nf2 * 2 + 1][0] = r2; bf[nf2 * 2 + 1][1] = r3;
        }
        #pragma unroll
        for (int mf = 0; mf < 2; mf++)
            #pragma unroll
            for (int nf = 0; nf < 4; nf++)
                MMA_FP16(acc[mf][nf], af[mf], bf[nf]);
    }
}

// ---------------------------------------------------------------------------
// Streamed GEMM (128x128 out, 256 threads, bf16 3-term): 3-stage cp.async ring.
// ---------------------------------------------------------------------------
__device__ __forceinline__ void gemm_stream(
    const __nv_bfloat16* __restrict__ Ah, const __nv_bfloat16* __restrict__ Al, int ldA,
    const __nv_bfloat16* __restrict__ Bh, const __nv_bfloat16* __restrict__ Bl, int ldB,
    int nk, float acc[4][4][4], uint32_t base, int tid,
    int arow, int brow, uint32_t acol0, uint32_t bcol0)
{
    __syncthreads();
    #pragma unroll
    for (int s = 0; s < 2; s++) {
        uint32_t st = base + (uint32_t)(s * 4 * T_BYTES);
        casync_tile(st,               (const uint16_t*)(Ah + s * 32), ldA, tid);
        casync_tile(st + T_BYTES,     (const uint16_t*)(Al + s * 32), ldA, tid);
        casync_tile(st + 2 * T_BYTES, (const uint16_t*)(Bh + s * 32), ldB, tid);
        casync_tile(st + 3 * T_BYTES, (const uint16_t*)(Bl + s * 32), ldB, tid);
        CP_COMMIT();
    }
    for (int ks = 0; ks < nk; ks++) {
        if (ks < nk - 1) CP_WAIT(1); else CP_WAIT(0);
        __syncthreads();
        if (ks + 2 < nk) {
            uint32_t st = base + (uint32_t)(((ks + 2) % 3) * 4 * T_BYTES);
            casync_tile(st,               (const uint16_t*)(Ah + (ks + 2) * 32), ldA, tid);
            casync_tile(st + T_BYTES,     (const uint16_t*)(Al + (ks + 2) * 32), ldA, tid);
            casync_tile(st + 2 * T_BYTES, (const uint16_t*)(Bh + (ks + 2) * 32), ldB, tid);
            casync_tile(st + 3 * T_BYTES, (const uint16_t*)(Bl + (ks + 2) * 32), ldB, tid);
            CP_COMMIT();
        }
        uint32_t st = base + (uint32_t)((ks % 3) * 4 * T_BYTES);
        mma_chunk(st, st + T_BYTES, st + 2 * T_BYTES, st + 3 * T_BYTES,
                  acc, arow, brow, acol0, bcol0);
    }
}

// ---------------------------------------------------------------------------
// A-resident fp16 1-term GEMM (attn phases A & C, 512 threads): B streamed.
// ---------------------------------------------------------------------------
__device__ __forceinline__ void gemm_ares1(
    uint32_t aTiles, const uint16_t* __restrict__ B, int ldB,
    uint32_t stg, float acc[2][4][4], int tid,
    int arow, int brow, uint32_t acol0, uint32_t bcol0)
{
    __syncthreads();
    #pragma unroll
    for (int s = 0; s < 2; s++) {
        casync_tile512(stg + (uint32_t)(s * T_BYTES), B + s * 32, ldB, tid);
        CP_COMMIT();
    }
    #pragma unroll
    for (int kc = 0; kc < 4; kc++) {
        if (kc < 3) CP_WAIT(1); else CP_WAIT(0);
        __syncthreads();
        if (kc + 2 < 4) {
            casync_tile512(stg + (uint32_t)(((kc + 2) % 3) * T_BYTES), B + (kc + 2) * 32, ldB, tid);
            CP_COMMIT();
        }
        mma_chunk1h(aTiles + (uint32_t)(kc * T_BYTES),
                    stg + (uint32_t)((kc % 3) * T_BYTES),
                    acc, arow, brow, acol0, bcol0);
    }
}

// 128-row fragment geometry (proj / wy; 8 warps 2x4)
#define FRAG_SETUP() \
    const int lane = threadIdx.x & 31, wid = threadIdx.x >> 5; \
    const int warp_m = wid >> 2, warp_n = wid & 3; \
    const int g = lane >> 2, t2 = (lane & 3) * 2; \
    (void)warp_m; (void)warp_n; (void)g; (void)t2
#define FROW(mf, h) (warp_m * 64 + (mf) * 16 + g + (h) * 8)
#define FCOL(nf)    (warp_n * 32 + (nf) * 8 + t2)
#define GEOM_SETUP() \
    const int arow = warp_m * 64 + (lane & 15); \
    const int brow = warp_n * 32 + (lane & 7) + ((lane >> 4) << 3); \
    const uint32_t acol0 = (uint32_t)((lane >> 4) << 4); \
    const uint32_t bcol0 = (uint32_t)(((lane >> 3) & 1) << 4)

// attn geometry (16 warps 4x4, 32x32 per warp)
#define FROW32(mf, h) (warp_m * 32 + (mf) * 16 + g + (h) * 8)

// ---------------------------------------------------------------------------
// Transpose + split x (bf16 hi/lo)
// ---------------------------------------------------------------------------
__global__ void k_xt(const float* __restrict__ x)
{
    __shared__ float t[32][33];
    const int b = blockIdx.z, c0 = blockIdx.y * 32, n0 = blockIdx.x * 32;
    const int tx = threadIdx.x, ty = threadIdx.y;
    const float* src = x + ((size_t)b * C_IN + c0) * NN + n0;
    #pragma unroll
    for (int i = 0; i < 32; i += 8) t[ty + i][tx] = src[(size_t)(ty + i) * NN + tx];
    __syncthreads();
    #pragma unroll
    for (int i = 0; i < 32; i += 8) {
        __nv_bfloat16 h, l;
        split1(t[tx][ty + i], h, l);
        d_xTh[b][n0 + ty + i][c0 + tx] = h;
        d_xTl[b][n0 + ty + i][c0 + tx] = l;
    }
}

// ---------------------------------------------------------------------------
// Convert weights to bf16 hi/lo planes
// ---------------------------------------------------------------------------
__global__ void k_wconv(const float* __restrict__ wth, const float* __restrict__ wph,
                        const float* __restrict__ wg,  const float* __restrict__ ww)
{
    int i = blockIdx.x * 256 + threadIdx.x;
    const float* src; __nv_bfloat16 *dh, *dl; int off;
    if (i < 32768)       { src = wth; dh = &d_wthh[0][0]; dl = &d_wthl[0][0]; off = i; }
    else if (i < 65536)  { src = wph; dh = &d_wphh[0][0]; dl = &d_wphl[0][0]; off = i - 32768; }
    else if (i < 98304)  { src = wg;  dh = &d_wgh[0][0];  dl = &d_wgl[0][0];  off = i - 65536; }
    else                 { src = ww;  dh = &d_wwh[0][0];  dl = &d_wwl[0][0];  off = i - 98304; }
    __nv_bfloat16 h, l;
    split1(src[off], h, l);
    dh[off] = h; dl[off] = l;
}

// ---------------------------------------------------------------------------
// Projections (bf16 3-term): theta, phi, g -> single fp16 planes
// ---------------------------------------------------------------------------
__global__ __launch_bounds__(256) void k_proj(
    const float* __restrict__ b_theta, const float* __restrict__ b_phi,
    const float* __restrict__ b_g)
{
    extern __shared__ char dsm[];
    const uint32_t base = (smem_u32(dsm) + 127u) & ~127u;
    const int b  = blockIdx.z;
    const int nT = blockIdx.x * 128;
    const __nv_bfloat16 *Wh, *Wl; const float* Bp;
    if (blockIdx.y == 0)      { Wh = &d_wthh[0][0]; Wl = &d_wthl[0][0]; Bp = b_theta; }
    else if (blockIdx.y == 1) { Wh = &d_wphh[0][0]; Wl = &d_wphl[0][0]; Bp = b_phi;   }
    else                      { Wh = &d_wgh[0][0];  Wl = &d_wgl[0][0];  Bp = b_g;     }

    FRAG_SETUP();
    GEOM_SETUP();
    const int tid = threadIdx.x;
    float acc[4][4][4] = {};
    gemm_stream(&d_xTh[b][nT][0], &d_xTl[b][nT][0], C_IN, Wh, Wl, C_IN,
                C_IN / 32, acc, base, tid, arow, brow, acol0, bcol0);

    if (blockIdx.y == 0) {
        // theta: single fp16 plane
        #pragma unroll
        for (int mf = 0; mf < 4; mf++)
            #pragma unroll
            for (int nf = 0; nf < 4; nf++) {
                int col = FCOL(nf);
                float2 bias = *(const float2*)&Bp[col];
                int r0 = FROW(mf, 0), r1 = FROW(mf, 1);
                *(uint32_t*)&d_th[b][nT + r0][col] =
                    packh2(acc[mf][nf][0] + bias.x, acc[mf][nf][1] + bias.y);
                *(uint32_t*)&d_th[b][nT + r1][col] =
                    packh2(acc[mf][nf][2] + bias.x, acc[mf][nf][3] + bias.y);
            }
    } else {
        float* stg = (float*)dsm;
        __syncthreads();
        #pragma unroll
        for (int mf = 0; mf < 4; mf++)
            #pragma unroll
            for (int nf = 0; nf < 4; nf++) {
                int col = FCOL(nf);
                int r0 = FROW(mf, 0), r1 = FROW(mf, 1);
                stg[col * STG_LD + r0]       = acc[mf][nf][0];
                stg[(col + 1) * STG_LD + r0] = acc[mf][nf][1];
                stg[col * STG_LD + r1]       = acc[mf][nf][2];
                stg[(col + 1) * STG_LD + r1] = acc[mf][nf][3];
            }
        __syncthreads();
        const int m0 = blockIdx.x * 32;
        const int t = threadIdx.x;
        if (blockIdx.y == 1) {
            #pragma unroll
            for (int ob = 0; ob < 4; ob++) {
                int oo = ob * 32 + (t & 31);
                #pragma unroll
                for (int i = 0; i < 4; i++) {
                    int wp = (t >> 5) + i * 8;
                    float2 a = *(const float2*)&stg[oo * STG_LD + 2 * wp];
                    float2 c = *(const float2*)&stg[oo * STG_LD + 64 + 2 * wp];
                    float v = fmaxf(fmaxf(a.x, a.y), fmaxf(c.x, c.y)) + Bp[oo];
                    d_phh[b][m0 + wp][oo] = __float2half_rn(v);
                }
            }
        } else {
            const int wp = t & 31;
            #pragma unroll
            for (int i = 0; i < 16; i++) {
                int o = (t >> 5) + i * 8;
                float2 a = *(const float2*)&stg[o * STG_LD + 2 * wp];
                float2 c = *(const float2*)&stg[o * STG_LD + 64 + 2 * wp];
                float v = fmaxf(fmaxf(a.x, a.y), fmaxf(c.x, c.y)) + Bp[o];
                d_gh[b][o][m0 + wp] = __float2half_rn(v);
            }
        }
    }
}

// ---------------------------------------------------------------------------
// Fused attention, 128-row n-tile, 512 threads.
// phase A: theta(single) x phi(single) — 1 MMA/k16  (NEW: theta single)
// phase C: P(single)     x g(single)   — 1 MMA/k16
// smem: [thA 40960][P 40960][Bstg 30720][red 2048]
// ---------------------------------------------------------------------------
#define ATTN_THA   0
#define ATTN_P     (4 * T_BYTES)
#define ATTN_BSTG  (ATTN_P + 4 * T_BYTES)
#define ATTN_RED   (ATTN_BSTG + 3 * T_BYTES)
#define DSM_ATTN   (ATTN_RED + 2048 + 128)

__global__ __launch_bounds__(512) void k_attn()
{
    extern __shared__ char dsm[];
    char* dsma = (char*)((((uintptr_t)dsm) + 127) & ~(uintptr_t)127);
    const uint32_t base = smem_u32(dsma);
    const uint32_t thA  = base + ATTN_THA;
    const uint32_t Pb   = base + ATTN_P;
    const uint32_t Bstg = base + ATTN_BSTG;
    float* redbuf = (float*)(dsma + ATTN_RED);

    const int b  = blockIdx.z;
    const int nT = blockIdx.x * 128;
    const int tid = threadIdx.x;
    const int lane = tid & 31, wid = tid >> 5;
    const int warp_m = wid >> 2, warp_n = wid & 3;
    const int g = lane >> 2, t2 = (lane & 3) * 2;
    const int arow = warp_m * 32 + (lane & 15);
    const int brow = warp_n * 32 + (lane & 7) + ((lane >> 4) << 3);
    const uint32_t acol0 = (uint32_t)((lane >> 4) << 4);
    const uint32_t bcol0 = (uint32_t)(((lane >> 3) & 1) << 4);

    // load theta tile (128 rows x 128 K, single fp16) once
    {
        const uint16_t* Ath = (const uint16_t*)&d_th[b][nT][0];
        #pragma unroll
        for (int kc = 0; kc < 4; kc++)
            casync_tile512(thA + (uint32_t)kc * T_BYTES, Ath + kc * 32, C_I, tid);
        CP_COMMIT();
        CP_WAIT(0);
        __syncthreads();
    }

    float yacc[2][4][4] = {};
    float ps[2][2] = {};

    for (int mt = 0; mt < 8; mt++) {
        const int mT = mt * 128;

        // phase A: scores (1 MMA/k16)
        float facc[2][4][4] = {};
        gemm_ares1(thA, (const uint16_t*)&d_phh[b][mT][0], C_I,
                   Bstg, facc, tid, arow, brow, acol0, bcol0);

        // phase B: exp + row partials + P -> smem single fp16 (warp_n owns chunk)
        const uint32_t Ph = Pb + (uint32_t)warp_n * T_BYTES;
        #pragma unroll
        for (int mf = 0; mf < 2; mf++) {
            const int r0 = FROW32(mf, 0), r1 = FROW32(mf, 1);
            #pragma unroll
            for (int nf = 0; nf < 4; nf++) {
                float e0 = __expf(facc[mf][nf][0]);
                float e1 = __expf(facc[mf][nf][1]);
                float e2 = __expf(facc[mf][nf][2]);
                float e3 = __expf(facc[mf][nf][3]);
                ps[mf][0] += e0 + e1;
                ps[mf][1] += e2 + e3;
                uint32_t hi0 = packh2(e0, e1);
                uint32_t hi1 = packh2(e2, e3);
                uint32_t off0 = (uint32_t)(r0 * T_STRIDE + (nf * 8 + t2) * 2);
                uint32_t off1 = (uint32_t)(r1 * T_STRIDE + (nf * 8 + t2) * 2);
                asm volatile("st.shared.b32 [%0], %1;" :: "r"(Ph + off0), "r"(hi0));
                asm volatile("st.shared.b32 [%0], %1;" :: "r"(Ph + off1), "r"(hi1));
            }
        }

        // phase C: yacc += P · g^T (1 MMA/k16)
        gemm_ares1(Pb, (const uint16_t*)&d_gh[b][0][mT], MM,
                   Bstg, yacc, tid, arow, brow, acol0, bcol0);
    }

    // epilogue: cross-warp row sums, normalize, write y planes (bf16 hi/lo)
    #pragma unroll
    for (int mf = 0; mf < 2; mf++)
        #pragma unroll
        for (int h = 0; h < 2; h++) {
            float v = ps[mf][h];
            v += __shfl_xor_sync(0xffffffffu, v, 1);
            v += __shfl_xor_sync(0xffffffffu, v, 2);
            if ((lane & 3) == 0) redbuf[warp_n * 128 + FROW32(mf, h)] = v;
        }
    __syncthreads();
    #pragma unroll
    for (int mf = 0; mf < 2; mf++)
        #pragma unroll
        for (int h = 0; h < 2; h++) {
            int row = FROW32(mf, h);
            float iv = 1.f / (redbuf[row] + redbuf[128 + row] +
                              redbuf[256 + row] + redbuf[384 + row]);
            #pragma unroll
            for (int nf = 0; nf < 4; nf++) {
                float c0 = yacc[mf][nf][2 * h]     * iv;
                float c1 = yacc[mf][nf][2 * h + 1] * iv;
                uint32_t lo, hi = pack2(c0, c1, lo);
                *(uint32_t*)&d_yh[b][nT + row][warp_n * 32 + nf * 8 + t2] = hi;
                *(uint32_t*)&d_yl[b][nT + row][warp_n * 32 + nf * 8 + t2] = lo;
            }
        }
}

// ---------------------------------------------------------------------------
// wy (bf16 3-term, as in R13 — BN-critical, stays hi/lo)
// ---------------------------------------------------------------------------
__global__ __launch_bounds__(256) void k_wy(const float* __restrict__ b_w)
{
    extern __shared__ char dsm[];
    const uint32_t base = (smem_u32(dsm) + 127u) & ~127u;
    const int b  = blockIdx.z;
    const int cT = blockIdx.y * 128;
    const int nT = blockIdx.x * 128;

    FRAG_SETUP();
    GEOM_SETUP();
    const int tid = threadIdx.x;
    float acc[4][4][4] = {};
    gemm_stream(&d_wwh[cT][0], &d_wwl[cT][0], C_I,
                &d_yh[b][nT][0], &d_yl[b][nT][0], C_I,
                C_I / 32, acc, base, tid, arow, brow, acol0, bcol0);

    const int sub = blockIdx.x * 4 + warp_n;
    #pragma unroll
    for (int mf = 0; mf < 4; mf++)
        #pragma unroll
        for (int h = 0; h < 2; h++) {
            int row = FROW(mf, h);
            int c = cT + row;
            float bias = b_w[c];
            float s = 0.f, ss = 0.f;
            #pragma unroll
            for (int nf = 0; nf < 4; nf++) {
                float c0 = acc[mf][nf][2 * h]     + bias;
                float c1 = acc[mf][nf][2 * h + 1] + bias;
                s += c0 + c1;
                ss += c0 * c0 + c1 * c1;
                *(float2*)&d_wy[b][c][nT + FCOL(nf)] = make_float2(c0, c1);
            }
            s  += __shfl_xor_sync(0xffffffffu, s, 1);
            s  += __shfl_xor_sync(0xffffffffu, s, 2);
            ss += __shfl_xor_sync(0xffffffffu, ss, 1);
            ss += __shfl_xor_sync(0xffffffffu, ss, 2);
            if ((lane & 3) == 0) { d_bns[b][c][sub] = s; d_bnss[b][c][sub] = ss; }
        }
}

// ---------------------------------------------------------------------------
// BN finalize
// ---------------------------------------------------------------------------
__global__ void k_bnfin(const float* __restrict__ gamma, const float* __restrict__ beta)
{
    const int c = blockIdx.x;
    const int t = threadIdx.x;
    float s = 0.f, ss = 0.f;
    #pragma unroll
    for (int i = 0; i < 4; i++) {
        int id = t + i * 256;
        int b = id >> 7, tile = id & 127;
        s  += d_bns [b][c][tile];
        ss += d_bnss[b][c][tile];
    }
    const int lane = t & 31, warp = t >> 5;
    #pragma unroll
    for (int o = 16; o > 0; o >>= 1) {
        s  += __shfl_xor_sync(0xffffffffu, s, o);
        ss += __shfl_xor_sync(0xffffffffu, ss, o);
    }
    __shared__ float rs[8], rss[8];
    if (lane == 0) { rs[warp] = s; rss[warp] = ss; }
    __syncthreads();
    if (t == 0) {
        float S = 0.f, SS = 0.f;
        #pragma unroll
        for (int i = 0; i < 8; i++) { S += rs[i]; SS += rss[i]; }
        const float invN = 1.f / (BATCH * NN);
        float mean = S * invN;
        float var  = SS * invN - mean * mean;
        float istd = rsqrtf(var + 1e-5f);
        float sc = gamma[c] * istd;
        d_scale[c] = sc;
        d_shift[c] = beta[c] - mean * sc;
    }
}

// ---------------------------------------------------------------------------
// out = BN(wy) + x
// ---------------------------------------------------------------------------
__global__ void k_final(const float* __restrict__ x, float* __restrict__ out)
{
    size_t i4 = (size_t)blockIdx.x * blockDim.x + threadIdx.x;
    if (i4 >= (size_t)BATCH * C_IN * NN / 4) return;
    int c = (int)((i4 >> 10) & (C_IN - 1));
    float sc = d_scale[c], sh = d_shift[c];
    float4 w  = ((const float4*)&d_wy[0][0][0])[i4];
    float4 xv = ((const float4*)x)[i4];
    float4 o;
    o.x = w.x * sc + sh + xv.x;
    o.y = w.y * sc + sh + xv.y;
    o.z = w.z * sc + sh + xv.z;
    o.w = w.w * sc + sh + xv.w;
    ((float4*)out)[i4] = o;
}

// ---------------------------------------------------------------------------
extern "C" void kernel_launch(void* const* d_in, const int* in_sizes, int n_in,
                              void* d_out, int out_size)
{
    const float* x       = (const float*)d_in[0];
    const float* w_g     = (const float*)d_in[1];
    const float* b_g     = (const float*)d_in[2];
    const float* w_theta = (const float*)d_in[3];
    const float* b_theta = (const float*)d_in[4];
    const float* w_phi   = (const float*)d_in[5];
    const float* b_phi   = (const float*)d_in[6];
    const float* w_w     = (const float*)d_in[7];
    const float* b_w     = (const float*)d_in[8];
    const float* gamma   = (const float*)d_in[9];
    const float* beta    = (const float*)d_in[10];
    float* out = (float*)d_out;

    cudaFuncSetAttribute(k_proj, cudaFuncAttributeMaxDynamicSharedMemorySize, DSM_GEMM);
    cudaFuncSetAttribute(k_attn, cudaFuncAttributeMaxDynamicSharedMemorySize, DSM_ATTN);
    cudaFuncSetAttribute(k_wy,   cudaFuncAttributeMaxDynamicSharedMemorySize, DSM_GEMM);

    k_xt   <<<dim3(NN / 32, C_IN / 32, BATCH), dim3(32, 8)>>>(x);
    k_wconv<<<512, 256>>>(w_theta, w_phi, w_g, w_w);
    k_proj <<<dim3(32, 3, BATCH), 256, DSM_GEMM>>>(b_theta, b_phi, b_g);
    k_attn <<<dim3(32, 1, BATCH), 512, DSM_ATTN>>>();
    k_wy   <<<dim3(32, 2, BATCH), 256, DSM_GEMM>>>(b_w);
    k_bnfin<<<C_IN, 256>>>(gamma, beta);
    k_final<<<(BATCH * C_IN * NN / 4 + 255) / 256, 256>>>(x, out);
}

// round 16
// speedup vs baseline: 1.8709x; 1.2283x over previous
#include <cuda_runtime.h>
#include <cuda_fp16.h>
#include <math.h>
#include <stdint.h>

#define BATCH 8
#define C_IN 256
#define C_I  128
#define NN   4096
#define MM   1024

// ---------------------------------------------------------------------------
// Scratch (all fp16 planes)
// x: hi/lo (exact-ish). W(theta/phi/g), w_w: single. theta/phi/g/P: single.
// y: hi/lo (BN-critical).
// ---------------------------------------------------------------------------
__device__ __align__(16) __half d_xTh[BATCH][NN][C_IN];
__device__ __align__(16) __half d_xTl[BATCH][NN][C_IN];
__device__ __align__(16) __half d_wth[C_I][C_IN];
__device__ __align__(16) __half d_wph[C_I][C_IN];
__device__ __align__(16) __half d_wg [C_I][C_IN];
__device__ __align__(16) __half d_ww [C_IN][C_I];
__device__ __align__(16) __half d_th [BATCH][NN][C_I];
__device__ __align__(16) __half d_phh[BATCH][MM][C_I];
__device__ __align__(16) __half d_gh [BATCH][C_I][MM];
__device__ __align__(16) __half d_yh [BATCH][NN][C_I];
__device__ __align__(16) __half d_yl [BATCH][NN][C_I];

__device__ float d_wy [BATCH][C_IN][NN];
__device__ float d_bns [BATCH][C_IN][128];
__device__ float d_bnss[BATCH][C_IN][128];
__device__ float d_scale[C_IN];
__device__ float d_shift[C_IN];

// ---------------------------------------------------------------------------
// helpers
// ---------------------------------------------------------------------------
__device__ __forceinline__ uint32_t smem_u32(const void* p) {
    uint32_t a;
    asm("{ .reg .u64 t; cvta.to.shared.u64 t, %1; cvt.u32.u64 %0, t; }" : "=r"(a) : "l"(p));
    return a;
}

#define LDSM_X4(r0, r1, r2, r3, addr) \
    asm volatile("ldmatrix.sync.aligned.m8n8.x4.shared.b16 {%0,%1,%2,%3}, [%4];" \
        : "=r"(r0), "=r"(r1), "=r"(r2), "=r"(r3) : "r"(addr))

#define MMA_FP16(c, a, b) \
    asm volatile("mma.sync.aligned.m16n8k16.row.col.f32.f16.f16.f32 " \
        "{%0,%1,%2,%3}, {%4,%5,%6,%7}, {%8,%9}, {%0,%1,%2,%3};" \
        : "+f"((c)[0]), "+f"((c)[1]), "+f"((c)[2]), "+f"((c)[3]) \
        : "r"((a)[0]), "r"((a)[1]), "r"((a)[2]), "r"((a)[3]), "r"((b)[0]), "r"((b)[1]))

#define CP_COMMIT()  asm volatile("cp.async.commit_group;" ::: "memory")
#define CP_WAIT(n)   asm volatile("cp.async.wait_group %0;" :: "n"(n) : "memory")

// fp16 single pair pack
__device__ __forceinline__ uint32_t packh2(float a, float b)
{
    __half ha = __float2half_rn(a), hb = __float2half_rn(b);
    return ((uint32_t)__half_as_ushort(hb) << 16) | __half_as_ushort(ha);
}

// fp16 hi/lo pair pack
__device__ __forceinline__ uint32_t pack2h(float a, float b, uint32_t& lo)
{
    __half ha = __float2half_rn(a), hb = __float2half_rn(b);
    __half la = __float2half_rn(a - __half2float(ha));
    __half lb = __float2half_rn(b - __half2float(hb));
    lo = ((uint32_t)__half_as_ushort(lb) << 16) | __half_as_ushort(la);
    return ((uint32_t)__half_as_ushort(hb) << 16) | __half_as_ushort(ha);
}

__device__ __forceinline__ void split1h(float v, __half& h, __half& l)
{
    h = __float2half_rn(v);
    l = __float2half_rn(v - __half2float(h));
}

#define T_STRIDE 80
#define T_BYTES  (128 * T_STRIDE)            // 10240 (128-row x 32-col tile)
#define DSM_GEMM (3 * 3 * T_BYTES + 128)     // 3 stages x 3 tiles
#define STG_LD   132

// async copy one 128x32 fp16 tile with 256 threads (2 x 16B per thread)
__device__ __forceinline__ void casync_tile(uint32_t dst, const uint16_t* __restrict__ src,
                                            int ld, int tid)
{
    #pragma unroll
    for (int i = 0; i < 2; i++) {
        int c = tid * 2 + i;
        int r = c >> 2, q = c & 3;
        const uint16_t* gp = src + (size_t)r * ld + q * 8;
        uint32_t sp = dst + (uint32_t)(r * T_STRIDE + q * 16);
        asm volatile("cp.async.cg.shared.global [%0], [%1], 16;" :: "r"(sp), "l"(gp) : "memory");
    }
}

// async copy one 128x32 fp16 tile with 512 threads (1 x 16B per thread)
__device__ __forceinline__ void casync_tile512(uint32_t dst, const uint16_t* __restrict__ src,
                                               int ld, int tid)
{
    int r = tid >> 2, q = tid & 3;
    const uint16_t* gp = src + (size_t)r * ld + q * 8;
    uint32_t sp = dst + (uint32_t)(r * T_STRIDE + q * 16);
    asm volatile("cp.async.cg.shared.global [%0], [%1], 16;" :: "r"(sp), "l"(gp) : "memory");
}

// one 32-K chunk, 4 m-frags, 2-term: A hi/lo + B single (proj, 256 thr)
__device__ __forceinline__ void mma_chunk2t(uint32_t tAh, uint32_t tAl, uint32_t tB,
                                            float acc[4][4][4],
                                            int arow, int brow, uint32_t acol0, uint32_t bcol0)
{
    #pragma unroll
    for (int kk = 0; kk < 2; kk++) {
        uint32_t ah[4][4], al[4][4], bf[4][2];
        const uint32_t ka = (uint32_t)(kk * 32) + acol0;
        const uint32_t kb = (uint32_t)(kk * 32) + bcol0;
        #pragma unroll
        for (int mf = 0; mf < 4; mf++) {
            uint32_t ad = (uint32_t)(arow + mf * 16) * T_STRIDE + ka;
            LDSM_X4(ah[mf][0], ah[mf][1], ah[mf][2], ah[mf][3], tAh + ad);
            LDSM_X4(al[mf][0], al[mf][1], al[mf][2], al[mf][3], tAl + ad);
        }
        #pragma unroll
        for (int nf2 = 0; nf2 < 2; nf2++) {
            uint32_t bd = (uint32_t)(brow + nf2 * 16) * T_STRIDE + kb;
            uint32_t r0, r1, r2, r3;
            LDSM_X4(r0, r1, r2, r3, tB + bd);
            bf[nf2 * 2][0] = r0; bf[nf2 * 2][1] = r1;
            bf[nf2 * 2 + 1][0] = r2; bf[nf2 * 2 + 1][1] = r3;
        }
        #pragma unroll
        for (int mf = 0; mf < 4; mf++)
            #pragma unroll
            for (int nf = 0; nf < 4; nf++) {
                MMA_FP16(acc[mf][nf], ah[mf], bf[nf]);
                MMA_FP16(acc[mf][nf], al[mf], bf[nf]);
            }
    }
}

// one 32-K chunk, 4 m-frags, 2-term: A single + B hi/lo (wy, 256 thr)
__device__ __forceinline__ void mma_chunk2b(uint32_t tA, uint32_t tBh, uint32_t tBl,
                                            float acc[4][4][4],
                                            int arow, int brow, uint32_t acol0, uint32_t bcol0)
{
    #pragma unroll
    for (int kk = 0; kk < 2; kk++) {
        uint32_t af[4][4], bh[4][2], bl[4][2];
        const uint32_t ka = (uint32_t)(kk * 32) + acol0;
        const uint32_t kb = (uint32_t)(kk * 32) + bcol0;
        #pragma unroll
        for (int mf = 0; mf < 4; mf++) {
            uint32_t ad = (uint32_t)(arow + mf * 16) * T_STRIDE + ka;
            LDSM_X4(af[mf][0], af[mf][1], af[mf][2], af[mf][3], tA + ad);
        }
        #pragma unroll
        for (int nf2 = 0; nf2 < 2; nf2++) {
            uint32_t bd = (uint32_t)(brow + nf2 * 16) * T_STRIDE + kb;
            uint32_t r0, r1, r2, r3;
            LDSM_X4(r0, r1, r2, r3, tBh + bd);
            bh[nf2 * 2][0] = r0; bh[nf2 * 2][1] = r1;
            bh[nf2 * 2 + 1][0] = r2; bh[nf2 * 2 + 1][1] = r3;
            LDSM_X4(r0, r1, r2, r3, tBl + bd);
            bl[nf2 * 2][0] = r0; bl[nf2 * 2][1] = r1;
            bl[nf2 * 2 + 1][0] = r2; bl[nf2 * 2 + 1][1] = r3;
        }
        #pragma unroll
        for (int mf = 0; mf < 4; mf++)
            #pragma unroll
            for (int nf = 0; nf < 4; nf++) {
                MMA_FP16(acc[mf][nf], af[mf], bh[nf]);
                MMA_FP16(acc[mf][nf], af[mf], bl[nf]);
            }
    }
}

// one 32-K chunk, 2 m-frags, 1-term (attn A & C, 512 thr)
__device__ __forceinline__ void mma_chunk1h(uint32_t tA, uint32_t tB,
                                            float acc[2][4][4],
                                            int arow, int brow, uint32_t acol0, uint32_t bcol0)
{
    #pragma unroll
    for (int kk = 0; kk < 2; kk++) {
        uint32_t af[2][4], bf[4][2];
        const uint32_t ka = (uint32_t)(kk * 32) + acol0;
        const uint32_t kb = (uint32_t)(kk * 32) + bcol0;
        #pragma unroll
        for (int mf = 0; mf < 2; mf++) {
            uint32_t ad = (uint32_t)(arow + mf * 16) * T_STRIDE + ka;
            LDSM_X4(af[mf][0], af[mf][1], af[mf][2], af[mf][3], tA + ad);
        }
        #pragma unroll
        for (int nf2 = 0; nf2 < 2; nf2++) {
            uint32_t bd = (uint32_t)(brow + nf2 * 16) * T_STRIDE + kb;
            uint32_t r0, r1, r2, r3;
            LDSM_X4(r0, r1, r2, r3, tB + bd);
            bf[nf2 * 2][0] = r0; bf[nf2 * 2][1] = r1;
            bf[nf2 * 2 + 1][0] = r2; bf[nf2 * 2 + 1][1] = r3;
        }
        #pragma unroll
        for (int mf = 0; mf < 2; mf++)
            #pragma unroll
            for (int nf = 0; nf < 4; nf++)
                MMA_FP16(acc[mf][nf], af[mf], bf[nf]);
    }
}

// ---------------------------------------------------------------------------
// Streamed 2-term GEMM, A hi/lo + B single (proj, 256 threads).
// ---------------------------------------------------------------------------
__device__ __forceinline__ void gemm_stream2(
    const uint16_t* __restrict__ Ah, const uint16_t* __restrict__ Al, int ldA,
    const uint16_t* __restrict__ B, int ldB,
    int nk, float acc[4][4][4], uint32_t base, int tid,
    int arow, int brow, uint32_t acol0, uint32_t bcol0)
{
    __syncthreads();
    #pragma unroll
    for (int s = 0; s < 2; s++) {
        uint32_t st = base + (uint32_t)(s * 3 * T_BYTES);
        casync_tile(st,               Ah + s * 32, ldA, tid);
        casync_tile(st + T_BYTES,     Al + s * 32, ldA, tid);
        casync_tile(st + 2 * T_BYTES, B  + s * 32, ldB, tid);
        CP_COMMIT();
    }
    for (int ks = 0; ks < nk; ks++) {
        if (ks < nk - 1) CP_WAIT(1); else CP_WAIT(0);
        __syncthreads();
        if (ks + 2 < nk) {
            uint32_t st = base + (uint32_t)(((ks + 2) % 3) * 3 * T_BYTES);
            casync_tile(st,               Ah + (ks + 2) * 32, ldA, tid);
            casync_tile(st + T_BYTES,     Al + (ks + 2) * 32, ldA, tid);
            casync_tile(st + 2 * T_BYTES, B  + (ks + 2) * 32, ldB, tid);
            CP_COMMIT();
        }
        uint32_t st = base + (uint32_t)((ks % 3) * 3 * T_BYTES);
        mma_chunk2t(st, st + T_BYTES, st + 2 * T_BYTES, acc, arow, brow, acol0, bcol0);
    }
}

// ---------------------------------------------------------------------------
// Streamed 2-term GEMM, A single + B hi/lo (wy, 256 threads).
// ---------------------------------------------------------------------------
__device__ __forceinline__ void gemm_stream2b(
    const uint16_t* __restrict__ A, int ldA,
    const uint16_t* __restrict__ Bh, const uint16_t* __restrict__ Bl, int ldB,
    int nk, float acc[4][4][4], uint32_t base, int tid,
    int arow, int brow, uint32_t acol0, uint32_t bcol0)
{
    __syncthreads();
    #pragma unroll
    for (int s = 0; s < 2; s++) {
        uint32_t st = base + (uint32_t)(s * 3 * T_BYTES);
        casync_tile(st,               A  + s * 32, ldA, tid);
        casync_tile(st + T_BYTES,     Bh + s * 32, ldB, tid);
        casync_tile(st + 2 * T_BYTES, Bl + s * 32, ldB, tid);
        CP_COMMIT();
    }
    for (int ks = 0; ks < nk; ks++) {
        if (ks < nk - 1) CP_WAIT(1); else CP_WAIT(0);
        __syncthreads();
        if (ks + 2 < nk) {
            uint32_t st = base + (uint32_t)(((ks + 2) % 3) * 3 * T_BYTES);
            casync_tile(st,               A  + (ks + 2) * 32, ldA, tid);
            casync_tile(st + T_BYTES,     Bh + (ks + 2) * 32, ldB, tid);
            casync_tile(st + 2 * T_BYTES, Bl + (ks + 2) * 32, ldB, tid);
            CP_COMMIT();
        }
        uint32_t st = base + (uint32_t)((ks % 3) * 3 * T_BYTES);
        mma_chunk2b(st, st + T_BYTES, st + 2 * T_BYTES, acc, arow, brow, acol0, bcol0);
    }
}

// ---------------------------------------------------------------------------
// A-resident fp16 1-term GEMM (attn phases A & C, 512 threads): B streamed.
// ---------------------------------------------------------------------------
__device__ __forceinline__ void gemm_ares1(
    uint32_t aTiles, const uint16_t* __restrict__ B, int ldB,
    uint32_t stg, float acc[2][4][4], int tid,
    int arow, int brow, uint32_t acol0, uint32_t bcol0)
{
    __syncthreads();
    #pragma unroll
    for (int s = 0; s < 2; s++) {
        casync_tile512(stg + (uint32_t)(s * T_BYTES), B + s * 32, ldB, tid);
        CP_COMMIT();
    }
    #pragma unroll
    for (int kc = 0; kc < 4; kc++) {
        if (kc < 3) CP_WAIT(1); else CP_WAIT(0);
        __syncthreads();
        if (kc + 2 < 4) {
            casync_tile512(stg + (uint32_t)(((kc + 2) % 3) * T_BYTES), B + (kc + 2) * 32, ldB, tid);
            CP_COMMIT();
        }
        mma_chunk1h(aTiles + (uint32_t)(kc * T_BYTES),
                    stg + (uint32_t)((kc % 3) * T_BYTES),
                    acc, arow, brow, acol0, bcol0);
    }
}

// 128-row fragment geometry (proj / wy; 8 warps 2x4)
#define FRAG_SETUP() \
    const int lane = threadIdx.x & 31, wid = threadIdx.x >> 5; \
    const int warp_m = wid >> 2, warp_n = wid & 3; \
    const int g = lane >> 2, t2 = (lane & 3) * 2; \
    (void)warp_m; (void)warp_n; (void)g; (void)t2
#define FROW(mf, h) (warp_m * 64 + (mf) * 16 + g + (h) * 8)
#define FCOL(nf)    (warp_n * 32 + (nf) * 8 + t2)
#define GEOM_SETUP() \
    const int arow = warp_m * 64 + (lane & 15); \
    const int brow = warp_n * 32 + (lane & 7) + ((lane >> 4) << 3); \
    const uint32_t acol0 = (uint32_t)((lane >> 4) << 4); \
    const uint32_t bcol0 = (uint32_t)(((lane >> 3) & 1) << 4)

// attn geometry (16 warps 4x4, 32x32 per warp)
#define FROW32(mf, h) (warp_m * 32 + (mf) * 16 + g + (h) * 8)

// ---------------------------------------------------------------------------
// Transpose + split x -> fp16 hi/lo planes
// ---------------------------------------------------------------------------
__global__ void k_xt(const float* __restrict__ x)
{
    __shared__ float t[32][33];
    const int b = blockIdx.z, c0 = blockIdx.y * 32, n0 = blockIdx.x * 32;
    const int tx = threadIdx.x, ty = threadIdx.y;
    const float* src = x + ((size_t)b * C_IN + c0) * NN + n0;
    #pragma unroll
    for (int i = 0; i < 32; i += 8) t[ty + i][tx] = src[(size_t)(ty + i) * NN + tx];
    __syncthreads();
    #pragma unroll
    for (int i = 0; i < 32; i += 8) {
        __half h, l;
        split1h(t[tx][ty + i], h, l);
        d_xTh[b][n0 + ty + i][c0 + tx] = h;
        d_xTl[b][n0 + ty + i][c0 + tx] = l;
    }
}

// ---------------------------------------------------------------------------
// Convert weights: theta/phi/g/w_w -> single fp16 (131072 elements)
// ---------------------------------------------------------------------------
__global__ void k_wconv(const float* __restrict__ wth, const float* __restrict__ wph,
                        const float* __restrict__ wg,  const float* __restrict__ ww)
{
    int i = blockIdx.x * 256 + threadIdx.x;
    if (i < 32768)      { (&d_wth[0][0])[i] = __float2half_rn(wth[i]); }
    else if (i < 65536) { int o = i - 32768; (&d_wph[0][0])[o] = __float2half_rn(wph[o]); }
    else if (i < 98304) { int o = i - 65536; (&d_wg[0][0])[o]  = __float2half_rn(wg[o]); }
    else                { int o = i - 98304; (&d_ww[0][0])[o]  = __float2half_rn(ww[o]); }
}

// ---------------------------------------------------------------------------
// Projections (fp16 2-term: x hi/lo x W single): theta/phi/g -> single fp16
// ---------------------------------------------------------------------------
__global__ __launch_bounds__(256) void k_proj(
    const float* __restrict__ b_theta, const float* __restrict__ b_phi,
    const float* __restrict__ b_g)
{
    extern __shared__ char dsm[];
    const uint32_t base = (smem_u32(dsm) + 127u) & ~127u;
    const int b  = blockIdx.z;
    const int nT = blockIdx.x * 128;
    const __half* Wp; const float* Bp;
    if (blockIdx.y == 0)      { Wp = &d_wth[0][0]; Bp = b_theta; }
    else if (blockIdx.y == 1) { Wp = &d_wph[0][0]; Bp = b_phi;   }
    else                      { Wp = &d_wg[0][0];  Bp = b_g;     }

    FRAG_SETUP();
    GEOM_SETUP();
    const int tid = threadIdx.x;
    float acc[4][4][4] = {};
    gemm_stream2((const uint16_t*)&d_xTh[b][nT][0], (const uint16_t*)&d_xTl[b][nT][0], C_IN,
                 (const uint16_t*)Wp, C_IN, C_IN / 32, acc, base, tid,
                 arow, brow, acol0, bcol0);

    if (blockIdx.y == 0) {
        #pragma unroll
        for (int mf = 0; mf < 4; mf++)
            #pragma unroll
            for (int nf = 0; nf < 4; nf++) {
                int col = FCOL(nf);
                float2 bias = *(const float2*)&Bp[col];
                int r0 = FROW(mf, 0), r1 = FROW(mf, 1);
                *(uint32_t*)&d_th[b][nT + r0][col] =
                    packh2(acc[mf][nf][0] + bias.x, acc[mf][nf][1] + bias.y);
                *(uint32_t*)&d_th[b][nT + r1][col] =
                    packh2(acc[mf][nf][2] + bias.x, acc[mf][nf][3] + bias.y);
            }
    } else {
        float* stg = (float*)dsm;
        __syncthreads();
        #pragma unroll
        for (int mf = 0; mf < 4; mf++)
            #pragma unroll
            for (int nf = 0; nf < 4; nf++) {
                int col = FCOL(nf);
                int r0 = FROW(mf, 0), r1 = FROW(mf, 1);
                stg[col * STG_LD + r0]       = acc[mf][nf][0];
                stg[(col + 1) * STG_LD + r0] = acc[mf][nf][1];
                stg[col * STG_LD + r1]       = acc[mf][nf][2];
                stg[(col + 1) * STG_LD + r1] = acc[mf][nf][3];
            }
        __syncthreads();
        const int m0 = blockIdx.x * 32;
        const int t = threadIdx.x;
        if (blockIdx.y == 1) {
            #pragma unroll
            for (int ob = 0; ob < 4; ob++) {
                int oo = ob * 32 + (t & 31);
                #pragma unroll
                for (int i = 0; i < 4; i++) {
                    int wp = (t >> 5) + i * 8;
                    float2 a = *(const float2*)&stg[oo * STG_LD + 2 * wp];
                    float2 c = *(const float2*)&stg[oo * STG_LD + 64 + 2 * wp];
                    float v = fmaxf(fmaxf(a.x, a.y), fmaxf(c.x, c.y)) + Bp[oo];
                    d_phh[b][m0 + wp][oo] = __float2half_rn(v);
                }
            }
        } else {
            const int wp = t & 31;
            #pragma unroll
            for (int i = 0; i < 16; i++) {
                int o = (t >> 5) + i * 8;
                float2 a = *(const float2*)&stg[o * STG_LD + 2 * wp];
                float2 c = *(const float2*)&stg[o * STG_LD + 64 + 2 * wp];
                float v = fmaxf(fmaxf(a.x, a.y), fmaxf(c.x, c.y)) + Bp[o];
                d_gh[b][o][m0 + wp] = __float2half_rn(v);
            }
        }
    }
}

// ---------------------------------------------------------------------------
// Fused attention (identical to R15): y epilogue -> fp16 hi/lo.
// phase A: theta(single) x phi(single) — 1 MMA/k16
// phase C: P(single)     x g(single)   — 1 MMA/k16
// ---------------------------------------------------------------------------
#define ATTN_THA   0
#define ATTN_P     (4 * T_BYTES)
#define ATTN_BSTG  (ATTN_P + 4 * T_BYTES)
#define ATTN_RED   (ATTN_BSTG + 3 * T_BYTES)
#define DSM_ATTN   (ATTN_RED + 2048 + 128)

__global__ __launch_bounds__(512) void k_attn()
{
    extern __shared__ char dsm[];
    char* dsma = (char*)((((uintptr_t)dsm) + 127) & ~(uintptr_t)127);
    const uint32_t base = smem_u32(dsma);
    const uint32_t thA  = base + ATTN_THA;
    const uint32_t Pb   = base + ATTN_P;
    const uint32_t Bstg = base + ATTN_BSTG;
    float* redbuf = (float*)(dsma + ATTN_RED);

    const int b  = blockIdx.z;
    const int nT = blockIdx.x * 128;
    const int tid = threadIdx.x;
    const int lane = tid & 31, wid = tid >> 5;
    const int warp_m = wid >> 2, warp_n = wid & 3;
    const int g = lane >> 2, t2 = (lane & 3) * 2;
    const int arow = warp_m * 32 + (lane & 15);
    const int brow = warp_n * 32 + (lane & 7) + ((lane >> 4) << 3);
    const uint32_t acol0 = (uint32_t)((lane >> 4) << 4);
    const uint32_t bcol0 = (uint32_t)(((lane >> 3) & 1) << 4);

    // load theta tile (128 rows x 128 K, single fp16) once
    {
        const uint16_t* Ath = (const uint16_t*)&d_th[b][nT][0];
        #pragma unroll
        for (int kc = 0; kc < 4; kc++)
            casync_tile512(thA + (uint32_t)kc * T_BYTES, Ath + kc * 32, C_I, tid);
        CP_COMMIT();
        CP_WAIT(0);
        __syncthreads();
    }

    float yacc[2][4][4] = {};
    float ps[2][2] = {};

    for (int mt = 0; mt < 8; mt++) {
        const int mT = mt * 128;

        // phase A: scores
        float facc[2][4][4] = {};
        gemm_ares1(thA, (const uint16_t*)&d_phh[b][mT][0], C_I,
                   Bstg, facc, tid, arow, brow, acol0, bcol0);

        // phase B: exp + row partials + P -> smem single fp16
        const uint32_t Ph = Pb + (uint32_t)warp_n * T_BYTES;
        #pragma unroll
        for (int mf = 0; mf < 2; mf++) {
            const int r0 = FROW32(mf, 0), r1 = FROW32(mf, 1);
            #pragma unroll
            for (int nf = 0; nf < 4; nf++) {
                float e0 = __expf(facc[mf][nf][0]);
                float e1 = __expf(facc[mf][nf][1]);
                float e2 = __expf(facc[mf][nf][2]);
                float e3 = __expf(facc[mf][nf][3]);
                ps[mf][0] += e0 + e1;
                ps[mf][1] += e2 + e3;
                uint32_t hi0 = packh2(e0, e1);
                uint32_t hi1 = packh2(e2, e3);
                uint32_t off0 = (uint32_t)(r0 * T_STRIDE + (nf * 8 + t2) * 2);
                uint32_t off1 = (uint32_t)(r1 * T_STRIDE + (nf * 8 + t2) * 2);
                asm volatile("st.shared.b32 [%0], %1;" :: "r"(Ph + off0), "r"(hi0));
                asm volatile("st.shared.b32 [%0], %1;" :: "r"(Ph + off1), "r"(hi1));
            }
        }

        // phase C: yacc += P · g^T
        gemm_ares1(Pb, (const uint16_t*)&d_gh[b][0][mT], MM,
                   Bstg, yacc, tid, arow, brow, acol0, bcol0);
    }

    // epilogue: row sums, normalize, write y (fp16 hi/lo)
    #pragma unroll
    for (int mf = 0; mf < 2; mf++)
        #pragma unroll
        for (int h = 0; h < 2; h++) {
            float v = ps[mf][h];
            v += __shfl_xor_sync(0xffffffffu, v, 1);
            v += __shfl_xor_sync(0xffffffffu, v, 2);
            if ((lane & 3) == 0) redbuf[warp_n * 128 + FROW32(mf, h)] = v;
        }
    __syncthreads();
    #pragma unroll
    for (int mf = 0; mf < 2; mf++)
        #pragma unroll
        for (int h = 0; h < 2; h++) {
            int row = FROW32(mf, h);
            float iv = 1.f / (redbuf[row] + redbuf[128 + row] +
                              redbuf[256 + row] + redbuf[384 + row]);
            #pragma unroll
            for (int nf = 0; nf < 4; nf++) {
                float c0 = yacc[mf][nf][2 * h]     * iv;
                float c1 = yacc[mf][nf][2 * h + 1] * iv;
                uint32_t lo, hi = pack2h(c0, c1, lo);
                *(uint32_t*)&d_yh[b][nT + row][warp_n * 32 + nf * 8 + t2] = hi;
                *(uint32_t*)&d_yl[b][nT + row][warp_n * 32 + nf * 8 + t2] = lo;
            }
        }
}

// ---------------------------------------------------------------------------
// wy: fp16 2-term (w_w single x y hi/lo); fused BN partials
// ---------------------------------------------------------------------------
__global__ __launch_bounds__(256) void k_wy(const float* __restrict__ b_w)
{
    extern __shared__ char dsm[];
    const uint32_t base = (smem_u32(dsm) + 127u) & ~127u;
    const int b  = blockIdx.z;
    const int cT = blockIdx.y * 128;
    const int nT = blockIdx.x * 128;

    FRAG_SETUP();
    GEOM_SETUP();
    const int tid = threadIdx.x;
    float acc[4][4][4] = {};
    gemm_stream2b((const uint16_t*)&d_ww[cT][0], C_I,
                  (const uint16_t*)&d_yh[b][nT][0], (const uint16_t*)&d_yl[b][nT][0], C_I,
                  C_I / 32, acc, base, tid, arow, brow, acol0, bcol0);

    const int sub = blockIdx.x * 4 + warp_n;
    #pragma unroll
    for (int mf = 0; mf < 4; mf++)
        #pragma unroll
        for (int h = 0; h < 2; h++) {
            int row = FROW(mf, h);
            int c = cT + row;
            float bias = b_w[c];
            float s = 0.f, ss = 0.f;
            #pragma unroll
            for (int nf = 0; nf < 4; nf++) {
                float c0 = acc[mf][nf][2 * h]     + bias;
                float c1 = acc[mf][nf][2 * h + 1] + bias;
                s += c0 + c1;
                ss += c0 * c0 + c1 * c1;
                *(float2*)&d_wy[b][c][nT + FCOL(nf)] = make_float2(c0, c1);
            }
            s  += __shfl_xor_sync(0xffffffffu, s, 1);
            s  += __shfl_xor_sync(0xffffffffu, s, 2);
            ss += __shfl_xor_sync(0xffffffffu, ss, 1);
            ss += __shfl_xor_sync(0xffffffffu, ss, 2);
            if ((lane & 3) == 0) { d_bns[b][c][sub] = s; d_bnss[b][c][sub] = ss; }
        }
}

// ---------------------------------------------------------------------------
// BN finalize
// ---------------------------------------------------------------------------
__global__ void k_bnfin(const float* __restrict__ gamma, const float* __restrict__ beta)
{
    const int c = blockIdx.x;
    const int t = threadIdx.x;
    float s = 0.f, ss = 0.f;
    #pragma unroll
    for (int i = 0; i < 4; i++) {
        int id = t + i * 256;
        int b = id >> 7, tile = id & 127;
        s  += d_bns [b][c][tile];
        ss += d_bnss[b][c][tile];
    }
    const int lane = t & 31, warp = t >> 5;
    #pragma unroll
    for (int o = 16; o > 0; o >>= 1) {
        s  += __shfl_xor_sync(0xffffffffu, s, o);
        ss += __shfl_xor_sync(0xffffffffu, ss, o);
    }
    __shared__ float rs[8], rss[8];
    if (lane == 0) { rs[warp] = s; rss[warp] = ss; }
    __syncthreads();
    if (t == 0) {
        float S = 0.f, SS = 0.f;
        #pragma unroll
        for (int i = 0; i < 8; i++) { S += rs[i]; SS += rss[i]; }
        const float invN = 1.f / (BATCH * NN);
        float mean = S * invN;
        float var  = SS * invN - mean * mean;
        float istd = rsqrtf(var + 1e-5f);
        float sc = gamma[c] * istd;
        d_scale[c] = sc;
        d_shift[c] = beta[c] - mean * sc;
    }
}

// ---------------------------------------------------------------------------
// out = BN(wy) + x
// ---------------------------------------------------------------------------
__global__ void k_final(const float* __restrict__ x, float* __restrict__ out)
{
    size_t i4 = (size_t)blockIdx.x * blockDim.x + threadIdx.x;
    if (i4 >= (size_t)BATCH * C_IN * NN / 4) return;
    int c = (int)((i4 >> 10) & (C_IN - 1));
    float sc = d_scale[c], sh = d_shift[c];
    float4 w  = ((const float4*)&d_wy[0][0][0])[i4];
    float4 xv = ((const float4*)x)[i4];
    float4 o;
    o.x = w.x * sc + sh + xv.x;
    o.y = w.y * sc + sh + xv.y;
    o.z = w.z * sc + sh + xv.z;
    o.w = w.w * sc + sh + xv.w;
    ((float4*)out)[i4] = o;
}

// ---------------------------------------------------------------------------
extern "C" void kernel_launch(void* const* d_in, const int* in_sizes, int n_in,
                              void* d_out, int out_size)
{
    const float* x       = (const float*)d_in[0];
    const float* w_g     = (const float*)d_in[1];
    const float* b_g     = (const float*)d_in[2];
    const float* w_theta = (const float*)d_in[3];
    const float* b_theta = (const float*)d_in[4];
    const float* w_phi   = (const float*)d_in[5];
    const float* b_phi   = (const float*)d_in[6];
    const float* w_w     = (const float*)d_in[7];
    const float* b_w     = (const float*)d_in[8];
    const float* gamma   = (const float*)d_in[9];
    const float* beta    = (const float*)d_in[10];
    float* out = (float*)d_out;

    cudaFuncSetAttribute(k_proj, cudaFuncAttributeMaxDynamicSharedMemorySize, DSM_GEMM);
    cudaFuncSetAttribute(k_attn, cudaFuncAttributeMaxDynamicSharedMemorySize, DSM_ATTN);
    cudaFuncSetAttribute(k_wy,   cudaFuncAttributeMaxDynamicSharedMemorySize, DSM_GEMM);

    k_xt   <<<dim3(NN / 32, C_IN / 32, BATCH), dim3(32, 8)>>>(x);
    k_wconv<<<512, 256>>>(w_theta, w_phi, w_g, w_w);
    k_proj <<<dim3(32, 3, BATCH), 256, DSM_GEMM>>>(b_theta, b_phi, b_g);
    k_attn <<<dim3(32, 1, BATCH), 512, DSM_ATTN>>>();
    k_wy   <<<dim3(32, 2, BATCH), 256, DSM_GEMM>>>(b_w);
    k_bnfin<<<C_IN, 256>>>(gamma, beta);
    k_final<<<(BATCH * C_IN * NN / 4 + 255) / 256, 256>>>(x, out);
}